// round 7
// baseline (speedup 1.0000x reference)
#include <cuda_runtime.h>
#include <cuda_bf16.h>
#include <math.h>
#include <stdint.h>

// Problem constants
#define TT      2048
#define DM      6144
#define NH      48
#define NKV     8
#define HD      128
#define QKV_N   8192
#define KV_OFF  DM
#define V_OFF   (DM + NKV*HD)
#define REP     (NH / NKV)
#define CLAMP_V 8.0f

// Scratch (static device globals)
__device__ float g_qkv[(size_t)TT * QKV_N];      // qkv activations (normal layout)
__device__ float g_attn[(size_t)TT * DM];        // attn out (K-permuted + tf32-rounded)
__device__ float g_xp[(size_t)TT * DM];          // perm+rna x
__device__ float g_wqkvp[(size_t)QKV_N * DM];    // perm+rna w_qkv
__device__ float g_woutp[(size_t)DM * DM];       // perm+rna w_out

// ===========================================================================
// Helpers
// ===========================================================================
__device__ __forceinline__ uint32_t smem_to_u32(const void* p) {
    uint32_t a;
    asm("{ .reg .u64 t; cvta.to.shared.u64 t, %1; cvt.u32.u64 %0, t; }"
        : "=r"(a) : "l"(p));
    return a;
}
__device__ __forceinline__ void cp16(uint32_t s, const void* g) {
    asm volatile("cp.async.cg.shared.global [%0], [%1], 16;"
                 :: "r"(s), "l"(g) : "memory");
}
__device__ __forceinline__ float ftf32(float x) {
    uint32_t o, i = __float_as_uint(x);
    asm("cvt.rna.tf32.f32 %0, %1;" : "=r"(o) : "r"(i));
    return __uint_as_float(o);
}
// tf32 m16n8k8 mma
__device__ __forceinline__ void mma8(float* d, const uint32_t* a, const uint32_t* b) {
    asm volatile(
        "mma.sync.aligned.m16n8k8.row.col.f32.tf32.tf32.f32 "
        "{%0,%1,%2,%3}, {%4,%5,%6,%7}, {%8,%9}, {%0,%1,%2,%3};"
        : "+f"(d[0]), "+f"(d[1]), "+f"(d[2]), "+f"(d[3])
        : "r"(a[0]), "r"(a[1]), "r"(a[2]), "r"(a[3]), "r"(b[0]), "r"(b[1]));
}
// bf16 m16n8k16 mma
__device__ __forceinline__ void mma16bf(float* d, const uint32_t* a, const uint32_t* b) {
    asm volatile(
        "mma.sync.aligned.m16n8k16.row.col.f32.bf16.bf16.f32 "
        "{%0,%1,%2,%3}, {%4,%5,%6,%7}, {%8,%9}, {%0,%1,%2,%3};"
        : "+f"(d[0]), "+f"(d[1]), "+f"(d[2]), "+f"(d[3])
        : "r"(a[0]), "r"(a[1]), "r"(a[2]), "r"(a[3]), "r"(b[0]), "r"(b[1]));
}
__device__ __forceinline__ uint32_t packsplit(float x, float y, uint32_t& lo) {
    __nv_bfloat16 hx = __float2bfloat16(x);
    __nv_bfloat16 hy = __float2bfloat16(y);
    float rx = x - __bfloat162float(hx);
    float ry = y - __bfloat162float(hy);
    __nv_bfloat16 lx = __float2bfloat16(rx);
    __nv_bfloat16 ly = __float2bfloat16(ry);
    lo = ((uint32_t)__bfloat16_as_ushort(ly) << 16) | __bfloat16_as_ushort(lx);
    return ((uint32_t)__bfloat16_as_ushort(hy) << 16) | __bfloat16_as_ushort(hx);
}
__device__ __forceinline__ float clmp(float v) {
    return fminf(fmaxf(v, -CLAMP_V), CLAMP_V);
}

// ===========================================================================
// Permute (within-8 interleave [0,4,1,5,2,6,3,7]) + rna-tf32 round.
// ===========================================================================
__global__ __launch_bounds__(256)
void perm_round_kernel(const float4* __restrict__ src, float4* __restrict__ dst, int n8)
{
    int g = blockIdx.x * blockDim.x + threadIdx.x;
    if (g < n8) {
        float4 i0 = src[2 * g];
        float4 i1 = src[2 * g + 1];
        float4 o0 = make_float4(ftf32(i0.x), ftf32(i1.x), ftf32(i0.y), ftf32(i1.y));
        float4 o1 = make_float4(ftf32(i0.z), ftf32(i1.z), ftf32(i0.w), ftf32(i1.w));
        dst[2 * g]     = o0;
        dst[2 * g + 1] = o1;
    }
}

// ===========================================================================
// tf32 mma.sync GEMM on K-PERMUTED pre-rounded operands.
// CTA tile 128x256, 8 warps (warp tile 64x64), 3-stage cp.async, one sync/iter.
// C[M,N] = A[M,K] * B[N,K]^T.  mode 1: fused RoPE+clamp epilogue.
// ===========================================================================
#define GPAD 40
#define ASZ  (128 * GPAD)           // floats per A stage
#define BSZ  (256 * GPAD)           // floats per B stage
#define GEMM_SMEM_BYTES ((3 * ASZ + 3 * BSZ) * 4)   // 184320

__global__ __launch_bounds__(256, 1)
void gemm_mma(const float* __restrict__ A, const float* __restrict__ B,
              float* __restrict__ C, int N, int K, int mode)
{
    extern __shared__ float sm[];
    const int tid  = threadIdx.x;
    const int wid  = tid >> 5, lane = tid & 31;
    const int wm   = (wid >> 2) * 64;       // 0 / 64
    const int wn   = (wid & 3) * 64;        // 0 / 64 / 128 / 192
    const int gr   = lane >> 2, tc = lane & 3;
    const int bm   = blockIdx.y * 128, bn = blockIdx.x * 256;

    const int ldr = tid >> 3;               // 0..31
    const int ldc = (tid & 7) * 4;          // 0..28

    const uint32_t sbase = smem_to_u32(sm);
    const int NS = K / 32;

    float acc[4][8][4];
#pragma unroll
    for (int i = 0; i < 4; i++)
#pragma unroll
        for (int j = 0; j < 8; j++)
#pragma unroll
            for (int r = 0; r < 4; r++) acc[i][j][r] = 0.f;

    auto loadTiles = [&](int k0, int st) {
#pragma unroll
        for (int v = 0; v < 4; v++) {       // A: 128 rows
            int row = ldr + v * 32;
            uint32_t sa = sbase + (uint32_t)(st * ASZ + row * GPAD + ldc) * 4;
            cp16(sa, A + (size_t)(bm + row) * K + k0 + ldc);
        }
#pragma unroll
        for (int v = 0; v < 8; v++) {       // B: 256 rows
            int row = ldr + v * 32;
            uint32_t sb = sbase + (uint32_t)(3 * ASZ + st * BSZ + row * GPAD + ldc) * 4;
            cp16(sb, B + (size_t)(bn + row) * K + k0 + ldc);
        }
        asm volatile("cp.async.commit_group;" ::: "memory");
    };

    // Prologue: stages 0, 1
    loadTiles(0, 0);
    loadTiles(32, 1);

    int st = 0;
    for (int s = 0; s < NS; s++) {
        asm volatile("cp.async.wait_group 1;" ::: "memory");
        __syncthreads();

        // Issue loads for s+2 into stage (st+2)%3 (safe: all warps past sync => done reading it)
        int nst = st + 2; if (nst >= 3) nst -= 3;
        if (s + 2 < NS) loadTiles((s + 2) * 32, nst);
        else asm volatile("cp.async.commit_group;" ::: "memory");

        const float* As_ = sm + st * ASZ;
        const float* Bs_ = sm + 3 * ASZ + st * BSZ;

#pragma unroll
        for (int ks = 0; ks < 4; ks++) {
            uint32_t a[4][4], b[8][2];
#pragma unroll
            for (int i = 0; i < 4; i++) {
                int abase = (wm + i * 16 + gr) * GPAD + ks * 8 + 2 * tc;
                float2 alo = *(const float2*)(As_ + abase);
                float2 ahi = *(const float2*)(As_ + abase + 8 * GPAD);
                a[i][0] = __float_as_uint(alo.x);
                a[i][1] = __float_as_uint(ahi.x);
                a[i][2] = __float_as_uint(alo.y);
                a[i][3] = __float_as_uint(ahi.y);
            }
#pragma unroll
            for (int j = 0; j < 8; j++) {
                int bbase = (wn + j * 8 + gr) * GPAD + ks * 8 + 2 * tc;
                float2 bv = *(const float2*)(Bs_ + bbase);
                b[j][0] = __float_as_uint(bv.x);
                b[j][1] = __float_as_uint(bv.y);
            }
#pragma unroll
            for (int i = 0; i < 4; i++)
#pragma unroll
                for (int j = 0; j < 8; j++)
                    mma8(acc[i][j], a[i], b[j]);
        }

        if (++st == 3) st = 0;
    }

    // Epilogue (pairs (c, c+1) per float2 == RoPE pairs when mode==1)
#pragma unroll
    for (int i = 0; i < 4; i++) {
#pragma unroll
        for (int j = 0; j < 8; j++) {
            int r = bm + wm + i * 16 + gr;
            int c = bn + wn + j * 8 + tc * 2;
            float2 v0 = make_float2(acc[i][j][0], acc[i][j][1]);
            float2 v1 = make_float2(acc[i][j][2], acc[i][j][3]);
            if (mode == 1) {
                if (c < V_OFF) {
                    int i64 = (c >> 1) & 63;
                    float inv = (float)pow(500000.0, -(double)i64 / 64.0);
                    float s0, c0;
                    sincosf((float)r * inv, &s0, &c0);
                    float a0 = v0.x, b0 = v0.y;
                    v0.x = clmp(a0 * c0 - b0 * s0);
                    v0.y = clmp(a0 * s0 + b0 * c0);
                    float s1, c1;
                    sincosf((float)(r + 8) * inv, &s1, &c1);
                    float a1 = v1.x, b1 = v1.y;
                    v1.x = clmp(a1 * c1 - b1 * s1);
                    v1.y = clmp(a1 * s1 + b1 * c1);
                } else {
                    v0.x = clmp(v0.x); v0.y = clmp(v0.y);
                    v1.x = clmp(v1.x); v1.y = clmp(v1.y);
                }
            }
            *(float2*)&C[(size_t)r * N + c]       = v0;
            *(float2*)&C[(size_t)(r + 8) * N + c] = v1;
        }
    }
}

// ===========================================================================
// Tensor-core flash attention (unchanged from R6; writes permuted + rounded).
// ===========================================================================
#define A_QH   0
#define A_QL   34816
#define A_KH   69632
#define A_KL   87040
#define A_VT   104448
#define A_VS   139264
#define A_PH   139264
#define A_SS   174080
#define A_PL   174080
#define A_STAT 208896
#define ATT_SMEM 210432

__global__ __launch_bounds__(256, 1)
void attn_mma_kernel(float* __restrict__ out)
{
    extern __shared__ char smem[];
    uint32_t* QHw = (uint32_t*)(smem + A_QH);
    uint32_t* QLw = (uint32_t*)(smem + A_QL);
    uint32_t* KHw = (uint32_t*)(smem + A_KH);
    uint32_t* KLw = (uint32_t*)(smem + A_KL);
    float*    VT  = (float*)(smem + A_VT);
    float*    VS  = (float*)(smem + A_VS);
    float*    PH  = (float*)(smem + A_PH);
    float*    SS  = (float*)(smem + A_SS);
    float*    PL  = SS;
    float* rowM = (float*)(smem + A_STAT);
    float* rowL = rowM + 128;
    float* rowA = rowL + 128;

    const int qb   = gridDim.x - 1 - blockIdx.x;
    const int h    = blockIdx.y;
    const int kh   = h / REP;
    const int tid  = threadIdx.x;
    const int wid  = tid >> 5, lane = tid & 31;
    const int gr   = lane >> 2, tc = lane & 3;
    const int m0   = (wid >> 1) * 32;
    const int wn   = (wid & 1) * 32;
    const int nv   = (wid & 1) * 64;
    const float scale = 0.088388347648318447f;

    {
        const float* qg = g_qkv + (size_t)(qb * 128) * QKV_N + h * HD;
#pragma unroll
        for (int i = 0; i < 16; i++) {
            int f = tid + i * 256;
            int r = f >> 5;
            int c = (f & 31) * 4;
            float4 v = *(const float4*)(qg + (size_t)r * QKV_N + c);
            uint32_t l0, l1;
            uint32_t h0 = packsplit(v.x, v.y, l0);
            uint32_t h1 = packsplit(v.z, v.w, l1);
            QHw[r * 68 + c / 2]     = h0;
            QHw[r * 68 + c / 2 + 1] = h1;
            QLw[r * 68 + c / 2]     = l0;
            QLw[r * 68 + c / 2 + 1] = l1;
        }
    }
    if (tid < 128) { rowM[tid] = -1e30f; rowL[tid] = 0.f; }

    float o[2][8][4];
#pragma unroll
    for (int mi = 0; mi < 2; mi++)
#pragma unroll
        for (int j = 0; j < 8; j++)
#pragma unroll
            for (int r = 0; r < 4; r++) o[mi][j][r] = 0.f;

    const int nkt = 2 * qb + 2;
    for (int kt = 0; kt < nkt; kt++) {
        __syncthreads();

        {
            const float* kg = g_qkv + (size_t)(kt * 64) * QKV_N + KV_OFF + kh * HD;
            const float* vg = g_qkv + (size_t)(kt * 64) * QKV_N + V_OFF  + kh * HD;
#pragma unroll
            for (int i = 0; i < 8; i++) {
                int f = tid + i * 256;
                int r = f >> 5;
                int c = (f & 31) * 4;
                float4 kv = *(const float4*)(kg + (size_t)r * QKV_N + c);
                uint32_t l0, l1;
                uint32_t h0 = packsplit(kv.x, kv.y, l0);
                uint32_t h1 = packsplit(kv.z, kv.w, l1);
                KHw[r * 68 + c / 2]     = h0;
                KHw[r * 68 + c / 2 + 1] = h1;
                KLw[r * 68 + c / 2]     = l0;
                KLw[r * 68 + c / 2 + 1] = l1;
                float4 vv = *(const float4*)(vg + (size_t)r * QKV_N + c);
                VS[r * 133 + c + 0] = vv.x;
                VS[r * 133 + c + 1] = vv.y;
                VS[r * 133 + c + 2] = vv.z;
                VS[r * 133 + c + 3] = vv.w;
            }
        }
        __syncthreads();

#pragma unroll
        for (int i = 0; i < 32; i++) {
            int widx = wid + 8 * i;
            int d = widx >> 1;
            int r = (widx & 1) * 32 + lane;
            VT[d * 68 + r] = ftf32(VS[r * 133 + d]);
        }

        float sacc[2][4][4];
#pragma unroll
        for (int mi = 0; mi < 2; mi++)
#pragma unroll
            for (int j = 0; j < 4; j++)
#pragma unroll
                for (int r = 0; r < 4; r++) sacc[mi][j][r] = 0.f;

#pragma unroll
        for (int ks = 0; ks < 8; ks++) {
            uint32_t ah[2][4], al[2][4];
#pragma unroll
            for (int mi = 0; mi < 2; mi++) {
                int base = (m0 + mi * 16 + gr) * 68 + ks * 8 + tc;
                ah[mi][0] = QHw[base];
                ah[mi][1] = QHw[base + 8 * 68];
                ah[mi][2] = QHw[base + 4];
                ah[mi][3] = QHw[base + 8 * 68 + 4];
                al[mi][0] = QLw[base];
                al[mi][1] = QLw[base + 8 * 68];
                al[mi][2] = QLw[base + 4];
                al[mi][3] = QLw[base + 8 * 68 + 4];
            }
            uint32_t bh[4][2], bl[4][2];
#pragma unroll
            for (int j = 0; j < 4; j++) {
                int base = (wn + j * 8 + gr) * 68 + ks * 8 + tc;
                bh[j][0] = KHw[base];
                bh[j][1] = KHw[base + 4];
                bl[j][0] = KLw[base];
                bl[j][1] = KLw[base + 4];
            }
#pragma unroll
            for (int mi = 0; mi < 2; mi++)
#pragma unroll
                for (int j = 0; j < 4; j++) {
                    mma16bf(sacc[mi][j], ah[mi], bh[j]);
                    mma16bf(sacc[mi][j], ah[mi], bl[j]);
                    mma16bf(sacc[mi][j], al[mi], bh[j]);
                }
        }

        const bool dg = (kt >= 2 * qb);
#pragma unroll
        for (int mi = 0; mi < 2; mi++) {
#pragma unroll
            for (int j = 0; j < 4; j++) {
                int rl0 = m0 + mi * 16 + gr;
                int cl  = wn + j * 8 + 2 * tc;
                float v0 = sacc[mi][j][0] * scale;
                float v1 = sacc[mi][j][1] * scale;
                float v2 = sacc[mi][j][2] * scale;
                float v3 = sacc[mi][j][3] * scale;
                if (dg) {
                    int rg0 = qb * 128 + rl0;
                    int cg  = kt * 64 + cl;
                    if (cg     > rg0)     v0 = -1e30f;
                    if (cg + 1 > rg0)     v1 = -1e30f;
                    if (cg     > rg0 + 8) v2 = -1e30f;
                    if (cg + 1 > rg0 + 8) v3 = -1e30f;
                }
                *(float2*)&SS[rl0 * 68 + cl]       = make_float2(v0, v1);
                *(float2*)&SS[(rl0 + 8) * 68 + cl] = make_float2(v2, v3);
            }
        }
        __syncthreads();

        if (tid < 128) {
            int r = tid;
            float mOld = rowM[r];
            float m = mOld;
            const float4* srow = (const float4*)(SS + r * 68);
#pragma unroll
            for (int jj = 0; jj < 16; jj++) {
                float4 s4 = srow[jj];
                m = fmaxf(m, fmaxf(fmaxf(s4.x, s4.y), fmaxf(s4.z, s4.w)));
            }
            float alpha = __expf(mOld - m);
            float l = 0.f;
#pragma unroll
            for (int jj = 0; jj < 16; jj++) {
                float4 s4 = srow[jj];
                float p0 = __expf(s4.x - m);
                float p1 = __expf(s4.y - m);
                float p2 = __expf(s4.z - m);
                float p3 = __expf(s4.w - m);
                l += (p0 + p1) + (p2 + p3);
                float h0 = ftf32(p0), h1 = ftf32(p1), h2 = ftf32(p2), h3 = ftf32(p3);
                float4 hv = make_float4(h0, h1, h2, h3);
                float4 lv = make_float4(ftf32(p0 - h0), ftf32(p1 - h1),
                                        ftf32(p2 - h2), ftf32(p3 - h3));
                *(float4*)&PH[r * 68 + jj * 4] = hv;
                *(float4*)&PL[r * 68 + jj * 4] = lv;
            }
            rowL[r] = rowL[r] * alpha + l;
            rowM[r] = m;
            rowA[r] = alpha;
        }
        __syncthreads();

#pragma unroll
        for (int mi = 0; mi < 2; mi++) {
            float am0 = rowA[m0 + mi * 16 + gr];
            float am1 = rowA[m0 + mi * 16 + gr + 8];
#pragma unroll
            for (int j = 0; j < 8; j++) {
                o[mi][j][0] *= am0; o[mi][j][1] *= am0;
                o[mi][j][2] *= am1; o[mi][j][3] *= am1;
            }
        }
#pragma unroll
        for (int ks = 0; ks < 8; ks++) {
            uint32_t ap[2][4], alr[2][4];
#pragma unroll
            for (int mi = 0; mi < 2; mi++) {
                int base = (m0 + mi * 16 + gr) * 68 + ks * 8 + tc;
                ap[mi][0]  = __float_as_uint(PH[base]);
                ap[mi][1]  = __float_as_uint(PH[base + 8 * 68]);
                ap[mi][2]  = __float_as_uint(PH[base + 4]);
                ap[mi][3]  = __float_as_uint(PH[base + 8 * 68 + 4]);
                alr[mi][0] = __float_as_uint(PL[base]);
                alr[mi][1] = __float_as_uint(PL[base + 8 * 68]);
                alr[mi][2] = __float_as_uint(PL[base + 4]);
                alr[mi][3] = __float_as_uint(PL[base + 8 * 68 + 4]);
            }
#pragma unroll
            for (int j = 0; j < 8; j++) {
                int base = (nv + j * 8 + gr) * 68 + ks * 8 + tc;
                uint32_t b[2];
                b[0] = __float_as_uint(VT[base]);
                b[1] = __float_as_uint(VT[base + 4]);
#pragma unroll
                for (int mi = 0; mi < 2; mi++) {
                    mma8(o[mi][j], ap[mi], b);
                    mma8(o[mi][j], alr[mi], b);
                }
            }
        }
    }

    // normalize + rna-round + K-PERMUTED store
    const int p0 = (tc < 2) ? 4 * tc     : 4 * tc - 7;
    const int p1 = (tc < 2) ? 4 * tc + 2 : 4 * tc - 5;
#pragma unroll
    for (int mi = 0; mi < 2; mi++) {
        int rl0 = m0 + mi * 16 + gr;
        float inv0 = 1.f / rowL[rl0];
        float inv1 = 1.f / rowL[rl0 + 8];
        int rg0 = qb * 128 + rl0;
#pragma unroll
        for (int j = 0; j < 8; j++) {
            int gbase = h * HD + nv + j * 8;
            float* d0 = out + (size_t)rg0 * DM + gbase;
            float* d1 = out + (size_t)(rg0 + 8) * DM + gbase;
            d0[p0] = ftf32(o[mi][j][0] * inv0);
            d0[p1] = ftf32(o[mi][j][1] * inv0);
            d1[p0] = ftf32(o[mi][j][2] * inv1);
            d1[p1] = ftf32(o[mi][j][3] * inv1);
        }
    }
}

// ===========================================================================
// Host side
// ===========================================================================
extern "C" void kernel_launch(void* const* d_in, const int* in_sizes, int n_in,
                              void* d_out, int out_size)
{
    const float* x     = (const float*)d_in[0];
    const float* w_qkv = (const float*)d_in[2];
    const float* w_out = (const float*)d_in[3];
    float* out = (float*)d_out;

    float *qkv, *attn, *xp, *wqkvp, *woutp;
    cudaGetSymbolAddress((void**)&qkv,   g_qkv);
    cudaGetSymbolAddress((void**)&attn,  g_attn);
    cudaGetSymbolAddress((void**)&xp,    g_xp);
    cudaGetSymbolAddress((void**)&wqkvp, g_wqkvp);
    cudaGetSymbolAddress((void**)&woutp, g_woutp);

    cudaFuncSetAttribute(gemm_mma, cudaFuncAttributeMaxDynamicSharedMemorySize,
                         GEMM_SMEM_BYTES);
    cudaFuncSetAttribute(attn_mma_kernel, cudaFuncAttributeMaxDynamicSharedMemorySize,
                         ATT_SMEM);

    // 0) permute + rna-round GEMM operands
    {
        int n8x = TT * DM / 8;
        perm_round_kernel<<<(n8x + 255) / 256, 256>>>((const float4*)x, (float4*)xp, n8x);
        int n8q = QKV_N * DM / 8;
        perm_round_kernel<<<(n8q + 255) / 256, 256>>>((const float4*)w_qkv, (float4*)wqkvp, n8q);
        int n8o = DM * DM / 8;
        perm_round_kernel<<<(n8o + 255) / 256, 256>>>((const float4*)w_out, (float4*)woutp, n8o);
    }

    // 1) QKV projection + fused RoPE/clamp epilogue
    {
        dim3 grid(QKV_N / 256, TT / 128);
        gemm_mma<<<grid, 256, GEMM_SMEM_BYTES>>>(xp, wqkvp, qkv, QKV_N, DM, 1);
    }

    // 2) Tensor-core flash attention (writes permuted + rounded)
    {
        dim3 grid(TT / 128, NH);
        attn_mma_kernel<<<grid, 256, ATT_SMEM>>>(attn);
    }

    // 3) Output projection
    {
        dim3 grid(DM / 256, TT / 128);
        gemm_mma<<<grid, 256, GEMM_SMEM_BYTES>>>(attn, woutp, out, DM, DM, 0);
    }
}

// round 8
// speedup vs baseline: 1.1659x; 1.1659x over previous
#include <cuda_runtime.h>
#include <cuda_bf16.h>
#include <math.h>
#include <stdint.h>

// Problem constants
#define TT      2048
#define DM      6144
#define NH      48
#define NKV     8
#define HD      128
#define QKV_N   8192
#define KV_OFF  DM
#define V_OFF   (DM + NKV*HD)
#define REP     (NH / NKV)
#define CLAMP_V 8.0f

// Scratch (static device globals)
__device__ float g_qkv[(size_t)TT * QKV_N];
__device__ float g_attn[(size_t)TT * DM];
__device__ float g_xp[(size_t)TT * DM];
__device__ float g_wqkvp[(size_t)QKV_N * DM];
__device__ float g_woutp[(size_t)DM * DM];

// ===========================================================================
// Helpers
// ===========================================================================
__device__ __forceinline__ uint32_t smem_to_u32(const void* p) {
    uint32_t a;
    asm("{ .reg .u64 t; cvta.to.shared.u64 t, %1; cvt.u32.u64 %0, t; }"
        : "=r"(a) : "l"(p));
    return a;
}
__device__ __forceinline__ void cp16(uint32_t s, const void* g) {
    asm volatile("cp.async.cg.shared.global [%0], [%1], 16;"
                 :: "r"(s), "l"(g) : "memory");
}
__device__ __forceinline__ float ftf32(float x) {
    uint32_t o, i = __float_as_uint(x);
    asm("cvt.rna.tf32.f32 %0, %1;" : "=r"(o) : "r"(i));
    return __uint_as_float(o);
}
__device__ __forceinline__ void mma8(float* d, const uint32_t* a, const uint32_t* b) {
    asm volatile(
        "mma.sync.aligned.m16n8k8.row.col.f32.tf32.tf32.f32 "
        "{%0,%1,%2,%3}, {%4,%5,%6,%7}, {%8,%9}, {%0,%1,%2,%3};"
        : "+f"(d[0]), "+f"(d[1]), "+f"(d[2]), "+f"(d[3])
        : "r"(a[0]), "r"(a[1]), "r"(a[2]), "r"(a[3]), "r"(b[0]), "r"(b[1]));
}
__device__ __forceinline__ void mma16bf(float* d, const uint32_t* a, const uint32_t* b) {
    asm volatile(
        "mma.sync.aligned.m16n8k16.row.col.f32.bf16.bf16.f32 "
        "{%0,%1,%2,%3}, {%4,%5,%6,%7}, {%8,%9}, {%0,%1,%2,%3};"
        : "+f"(d[0]), "+f"(d[1]), "+f"(d[2]), "+f"(d[3])
        : "r"(a[0]), "r"(a[1]), "r"(a[2]), "r"(a[3]), "r"(b[0]), "r"(b[1]));
}
__device__ __forceinline__ uint32_t packsplit(float x, float y, uint32_t& lo) {
    __nv_bfloat16 hx = __float2bfloat16(x);
    __nv_bfloat16 hy = __float2bfloat16(y);
    float rx = x - __bfloat162float(hx);
    float ry = y - __bfloat162float(hy);
    __nv_bfloat16 lx = __float2bfloat16(rx);
    __nv_bfloat16 ly = __float2bfloat16(ry);
    lo = ((uint32_t)__bfloat16_as_ushort(ly) << 16) | __bfloat16_as_ushort(lx);
    return ((uint32_t)__bfloat16_as_ushort(hy) << 16) | __bfloat16_as_ushort(hx);
}
__device__ __forceinline__ float clmp(float v) {
    return fminf(fmaxf(v, -CLAMP_V), CLAMP_V);
}

// ===========================================================================
// Permute (within-8 interleave [0,4,1,5,2,6,3,7]) + rna-tf32 round.
// ===========================================================================
__global__ __launch_bounds__(256)
void perm_round_kernel(const float4* __restrict__ src, float4* __restrict__ dst, int n8)
{
    int g = blockIdx.x * blockDim.x + threadIdx.x;
    if (g < n8) {
        float4 i0 = src[2 * g];
        float4 i1 = src[2 * g + 1];
        float4 o0 = make_float4(ftf32(i0.x), ftf32(i1.x), ftf32(i0.y), ftf32(i1.y));
        float4 o1 = make_float4(ftf32(i0.z), ftf32(i1.z), ftf32(i0.w), ftf32(i1.w));
        dst[2 * g]     = o0;
        dst[2 * g + 1] = o1;
    }
}

// ===========================================================================
// tf32 mma.sync GEMM on K-PERMUTED pre-rounded operands.
// CTA tile 128x128, 128 threads (4 warps, warp tile 64x64), 2 CTAs/SM,
// double-buffered cp.async, BK=32. C[M,N] = A[M,K] * B[N,K]^T.
// mode 1: fused RoPE+clamp epilogue.
// ===========================================================================
#define GPAD 40
#define TSZ  (128 * GPAD)                      // floats per operand per stage
#define GEMM_SMEM_BYTES (4 * TSZ * 4)          // 2 stages x 2 operands = 81920

__global__ __launch_bounds__(128, 2)
void gemm_mma(const float* __restrict__ A, const float* __restrict__ B,
              float* __restrict__ C, int N, int K, int mode)
{
    extern __shared__ float sm[];
    const int tid  = threadIdx.x;
    const int wid  = tid >> 5, lane = tid & 31;
    const int wm   = (wid >> 1) * 64;       // 0 / 64
    const int wn   = (wid & 1) * 64;        // 0 / 64
    const int gr   = lane >> 2, tc = lane & 3;
    const int bm   = blockIdx.y * 128, bn = blockIdx.x * 128;

    const int ldr = tid >> 3;               // 0..15
    const int ldc = (tid & 7) * 4;          // 0..28

    const uint32_t sbase = smem_to_u32(sm);
    const int NS = K / 32;

    float acc[4][8][4];
#pragma unroll
    for (int i = 0; i < 4; i++)
#pragma unroll
        for (int j = 0; j < 8; j++)
#pragma unroll
            for (int r = 0; r < 4; r++) acc[i][j][r] = 0.f;

    auto loadTiles = [&](int k0, int buf) {
#pragma unroll
        for (int v = 0; v < 8; v++) {
            int row = ldr + v * 16;
            uint32_t sa = sbase + (uint32_t)(buf * TSZ + row * GPAD + ldc) * 4;
            cp16(sa, A + (size_t)(bm + row) * K + k0 + ldc);
            uint32_t sb = sbase + (uint32_t)(2 * TSZ + buf * TSZ + row * GPAD + ldc) * 4;
            cp16(sb, B + (size_t)(bn + row) * K + k0 + ldc);
        }
        asm volatile("cp.async.commit_group;" ::: "memory");
    };

    loadTiles(0, 0);

    for (int s = 0; s < NS; s++) {
        const int buf = s & 1;
        if (s + 1 < NS) {
            loadTiles((s + 1) * 32, buf ^ 1);
            asm volatile("cp.async.wait_group 1;" ::: "memory");
        } else {
            asm volatile("cp.async.wait_group 0;" ::: "memory");
        }
        __syncthreads();

        const float* As_ = sm + buf * TSZ;
        const float* Bs_ = sm + 2 * TSZ + buf * TSZ;

#pragma unroll
        for (int ks = 0; ks < 4; ks++) {
            uint32_t a[4][4], b[8][2];
#pragma unroll
            for (int i = 0; i < 4; i++) {
                int abase = (wm + i * 16 + gr) * GPAD + ks * 8 + 2 * tc;
                float2 alo = *(const float2*)(As_ + abase);
                float2 ahi = *(const float2*)(As_ + abase + 8 * GPAD);
                a[i][0] = __float_as_uint(alo.x);
                a[i][1] = __float_as_uint(ahi.x);
                a[i][2] = __float_as_uint(alo.y);
                a[i][3] = __float_as_uint(ahi.y);
            }
#pragma unroll
            for (int j = 0; j < 8; j++) {
                int bbase = (wn + j * 8 + gr) * GPAD + ks * 8 + 2 * tc;
                float2 bv = *(const float2*)(Bs_ + bbase);
                b[j][0] = __float_as_uint(bv.x);
                b[j][1] = __float_as_uint(bv.y);
            }
#pragma unroll
            for (int i = 0; i < 4; i++)
#pragma unroll
                for (int j = 0; j < 8; j++)
                    mma8(acc[i][j], a[i], b[j]);
        }
        __syncthreads();
    }

    // Epilogue (pairs (c, c+1) per float2 == RoPE pairs when mode==1)
#pragma unroll
    for (int i = 0; i < 4; i++) {
#pragma unroll
        for (int j = 0; j < 8; j++) {
            int r = bm + wm + i * 16 + gr;
            int c = bn + wn + j * 8 + tc * 2;
            float2 v0 = make_float2(acc[i][j][0], acc[i][j][1]);
            float2 v1 = make_float2(acc[i][j][2], acc[i][j][3]);
            if (mode == 1) {
                if (c < V_OFF) {
                    int i64 = (c >> 1) & 63;
                    float inv = (float)pow(500000.0, -(double)i64 / 64.0);
                    float s0, c0;
                    sincosf((float)r * inv, &s0, &c0);
                    float a0 = v0.x, b0 = v0.y;
                    v0.x = clmp(a0 * c0 - b0 * s0);
                    v0.y = clmp(a0 * s0 + b0 * c0);
                    float s1, c1;
                    sincosf((float)(r + 8) * inv, &s1, &c1);
                    float a1 = v1.x, b1 = v1.y;
                    v1.x = clmp(a1 * c1 - b1 * s1);
                    v1.y = clmp(a1 * s1 + b1 * c1);
                } else {
                    v0.x = clmp(v0.x); v0.y = clmp(v0.y);
                    v1.x = clmp(v1.x); v1.y = clmp(v1.y);
                }
            }
            *(float2*)&C[(size_t)r * N + c]       = v0;
            *(float2*)&C[(size_t)(r + 8) * N + c] = v1;
        }
    }
}

// ===========================================================================
// Tensor-core flash attention (unchanged; writes permuted + rounded).
// ===========================================================================
#define A_QH   0
#define A_QL   34816
#define A_KH   69632
#define A_KL   87040
#define A_VT   104448
#define A_VS   139264
#define A_PH   139264
#define A_SS   174080
#define A_PL   174080
#define A_STAT 208896
#define ATT_SMEM 210432

__global__ __launch_bounds__(256, 1)
void attn_mma_kernel(float* __restrict__ out)
{
    extern __shared__ char smem[];
    uint32_t* QHw = (uint32_t*)(smem + A_QH);
    uint32_t* QLw = (uint32_t*)(smem + A_QL);
    uint32_t* KHw = (uint32_t*)(smem + A_KH);
    uint32_t* KLw = (uint32_t*)(smem + A_KL);
    float*    VT  = (float*)(smem + A_VT);
    float*    VS  = (float*)(smem + A_VS);
    float*    PH  = (float*)(smem + A_PH);
    float*    SS  = (float*)(smem + A_SS);
    float*    PL  = SS;
    float* rowM = (float*)(smem + A_STAT);
    float* rowL = rowM + 128;
    float* rowA = rowL + 128;

    const int qb   = gridDim.x - 1 - blockIdx.x;
    const int h    = blockIdx.y;
    const int kh   = h / REP;
    const int tid  = threadIdx.x;
    const int wid  = tid >> 5, lane = tid & 31;
    const int gr   = lane >> 2, tc = lane & 3;
    const int m0   = (wid >> 1) * 32;
    const int wn   = (wid & 1) * 32;
    const int nv   = (wid & 1) * 64;
    const float scale = 0.088388347648318447f;

    {
        const float* qg = g_qkv + (size_t)(qb * 128) * QKV_N + h * HD;
#pragma unroll
        for (int i = 0; i < 16; i++) {
            int f = tid + i * 256;
            int r = f >> 5;
            int c = (f & 31) * 4;
            float4 v = *(const float4*)(qg + (size_t)r * QKV_N + c);
            uint32_t l0, l1;
            uint32_t h0 = packsplit(v.x, v.y, l0);
            uint32_t h1 = packsplit(v.z, v.w, l1);
            QHw[r * 68 + c / 2]     = h0;
            QHw[r * 68 + c / 2 + 1] = h1;
            QLw[r * 68 + c / 2]     = l0;
            QLw[r * 68 + c / 2 + 1] = l1;
        }
    }
    if (tid < 128) { rowM[tid] = -1e30f; rowL[tid] = 0.f; }

    float o[2][8][4];
#pragma unroll
    for (int mi = 0; mi < 2; mi++)
#pragma unroll
        for (int j = 0; j < 8; j++)
#pragma unroll
            for (int r = 0; r < 4; r++) o[mi][j][r] = 0.f;

    const int nkt = 2 * qb + 2;
    for (int kt = 0; kt < nkt; kt++) {
        __syncthreads();

        {
            const float* kg = g_qkv + (size_t)(kt * 64) * QKV_N + KV_OFF + kh * HD;
            const float* vg = g_qkv + (size_t)(kt * 64) * QKV_N + V_OFF  + kh * HD;
#pragma unroll
            for (int i = 0; i < 8; i++) {
                int f = tid + i * 256;
                int r = f >> 5;
                int c = (f & 31) * 4;
                float4 kv = *(const float4*)(kg + (size_t)r * QKV_N + c);
                uint32_t l0, l1;
                uint32_t h0 = packsplit(kv.x, kv.y, l0);
                uint32_t h1 = packsplit(kv.z, kv.w, l1);
                KHw[r * 68 + c / 2]     = h0;
                KHw[r * 68 + c / 2 + 1] = h1;
                KLw[r * 68 + c / 2]     = l0;
                KLw[r * 68 + c / 2 + 1] = l1;
                float4 vv = *(const float4*)(vg + (size_t)r * QKV_N + c);
                VS[r * 133 + c + 0] = vv.x;
                VS[r * 133 + c + 1] = vv.y;
                VS[r * 133 + c + 2] = vv.z;
                VS[r * 133 + c + 3] = vv.w;
            }
        }
        __syncthreads();

#pragma unroll
        for (int i = 0; i < 32; i++) {
            int widx = wid + 8 * i;
            int d = widx >> 1;
            int r = (widx & 1) * 32 + lane;
            VT[d * 68 + r] = ftf32(VS[r * 133 + d]);
        }

        float sacc[2][4][4];
#pragma unroll
        for (int mi = 0; mi < 2; mi++)
#pragma unroll
            for (int j = 0; j < 4; j++)
#pragma unroll
                for (int r = 0; r < 4; r++) sacc[mi][j][r] = 0.f;

#pragma unroll
        for (int ks = 0; ks < 8; ks++) {
            uint32_t ah[2][4], al[2][4];
#pragma unroll
            for (int mi = 0; mi < 2; mi++) {
                int base = (m0 + mi * 16 + gr) * 68 + ks * 8 + tc;
                ah[mi][0] = QHw[base];
                ah[mi][1] = QHw[base + 8 * 68];
                ah[mi][2] = QHw[base + 4];
                ah[mi][3] = QHw[base + 8 * 68 + 4];
                al[mi][0] = QLw[base];
                al[mi][1] = QLw[base + 8 * 68];
                al[mi][2] = QLw[base + 4];
                al[mi][3] = QLw[base + 8 * 68 + 4];
            }
            uint32_t bh[4][2], bl[4][2];
#pragma unroll
            for (int j = 0; j < 4; j++) {
                int base = (wn + j * 8 + gr) * 68 + ks * 8 + tc;
                bh[j][0] = KHw[base];
                bh[j][1] = KHw[base + 4];
                bl[j][0] = KLw[base];
                bl[j][1] = KLw[base + 4];
            }
#pragma unroll
            for (int mi = 0; mi < 2; mi++)
#pragma unroll
                for (int j = 0; j < 4; j++) {
                    mma16bf(sacc[mi][j], ah[mi], bh[j]);
                    mma16bf(sacc[mi][j], ah[mi], bl[j]);
                    mma16bf(sacc[mi][j], al[mi], bh[j]);
                }
        }

        const bool dg = (kt >= 2 * qb);
#pragma unroll
        for (int mi = 0; mi < 2; mi++) {
#pragma unroll
            for (int j = 0; j < 4; j++) {
                int rl0 = m0 + mi * 16 + gr;
                int cl  = wn + j * 8 + 2 * tc;
                float v0 = sacc[mi][j][0] * scale;
                float v1 = sacc[mi][j][1] * scale;
                float v2 = sacc[mi][j][2] * scale;
                float v3 = sacc[mi][j][3] * scale;
                if (dg) {
                    int rg0 = qb * 128 + rl0;
                    int cg  = kt * 64 + cl;
                    if (cg     > rg0)     v0 = -1e30f;
                    if (cg + 1 > rg0)     v1 = -1e30f;
                    if (cg     > rg0 + 8) v2 = -1e30f;
                    if (cg + 1 > rg0 + 8) v3 = -1e30f;
                }
                *(float2*)&SS[rl0 * 68 + cl]       = make_float2(v0, v1);
                *(float2*)&SS[(rl0 + 8) * 68 + cl] = make_float2(v2, v3);
            }
        }
        __syncthreads();

        if (tid < 128) {
            int r = tid;
            float mOld = rowM[r];
            float m = mOld;
            const float4* srow = (const float4*)(SS + r * 68);
#pragma unroll
            for (int jj = 0; jj < 16; jj++) {
                float4 s4 = srow[jj];
                m = fmaxf(m, fmaxf(fmaxf(s4.x, s4.y), fmaxf(s4.z, s4.w)));
            }
            float alpha = __expf(mOld - m);
            float l = 0.f;
#pragma unroll
            for (int jj = 0; jj < 16; jj++) {
                float4 s4 = srow[jj];
                float p0 = __expf(s4.x - m);
                float p1 = __expf(s4.y - m);
                float p2 = __expf(s4.z - m);
                float p3 = __expf(s4.w - m);
                l += (p0 + p1) + (p2 + p3);
                float h0 = ftf32(p0), h1 = ftf32(p1), h2 = ftf32(p2), h3 = ftf32(p3);
                float4 hv = make_float4(h0, h1, h2, h3);
                float4 lv = make_float4(ftf32(p0 - h0), ftf32(p1 - h1),
                                        ftf32(p2 - h2), ftf32(p3 - h3));
                *(float4*)&PH[r * 68 + jj * 4] = hv;
                *(float4*)&PL[r * 68 + jj * 4] = lv;
            }
            rowL[r] = rowL[r] * alpha + l;
            rowM[r] = m;
            rowA[r] = alpha;
        }
        __syncthreads();

#pragma unroll
        for (int mi = 0; mi < 2; mi++) {
            float am0 = rowA[m0 + mi * 16 + gr];
            float am1 = rowA[m0 + mi * 16 + gr + 8];
#pragma unroll
            for (int j = 0; j < 8; j++) {
                o[mi][j][0] *= am0; o[mi][j][1] *= am0;
                o[mi][j][2] *= am1; o[mi][j][3] *= am1;
            }
        }
#pragma unroll
        for (int ks = 0; ks < 8; ks++) {
            uint32_t ap[2][4], alr[2][4];
#pragma unroll
            for (int mi = 0; mi < 2; mi++) {
                int base = (m0 + mi * 16 + gr) * 68 + ks * 8 + tc;
                ap[mi][0]  = __float_as_uint(PH[base]);
                ap[mi][1]  = __float_as_uint(PH[base + 8 * 68]);
                ap[mi][2]  = __float_as_uint(PH[base + 4]);
                ap[mi][3]  = __float_as_uint(PH[base + 8 * 68 + 4]);
                alr[mi][0] = __float_as_uint(PL[base]);
                alr[mi][1] = __float_as_uint(PL[base + 8 * 68]);
                alr[mi][2] = __float_as_uint(PL[base + 4]);
                alr[mi][3] = __float_as_uint(PL[base + 8 * 68 + 4]);
            }
#pragma unroll
            for (int j = 0; j < 8; j++) {
                int base = (nv + j * 8 + gr) * 68 + ks * 8 + tc;
                uint32_t b[2];
                b[0] = __float_as_uint(VT[base]);
                b[1] = __float_as_uint(VT[base + 4]);
#pragma unroll
                for (int mi = 0; mi < 2; mi++) {
                    mma8(o[mi][j], ap[mi], b);
                    mma8(o[mi][j], alr[mi], b);
                }
            }
        }
    }

    // normalize + rna-round + K-PERMUTED store
    const int p0 = (tc < 2) ? 4 * tc     : 4 * tc - 7;
    const int p1 = (tc < 2) ? 4 * tc + 2 : 4 * tc - 5;
#pragma unroll
    for (int mi = 0; mi < 2; mi++) {
        int rl0 = m0 + mi * 16 + gr;
        float inv0 = 1.f / rowL[rl0];
        float inv1 = 1.f / rowL[rl0 + 8];
        int rg0 = qb * 128 + rl0;
#pragma unroll
        for (int j = 0; j < 8; j++) {
            int gbase = h * HD + nv + j * 8;
            float* d0 = out + (size_t)rg0 * DM + gbase;
            float* d1 = out + (size_t)(rg0 + 8) * DM + gbase;
            d0[p0] = ftf32(o[mi][j][0] * inv0);
            d0[p1] = ftf32(o[mi][j][1] * inv0);
            d1[p0] = ftf32(o[mi][j][2] * inv1);
            d1[p1] = ftf32(o[mi][j][3] * inv1);
        }
    }
}

// ===========================================================================
// Host side
// ===========================================================================
extern "C" void kernel_launch(void* const* d_in, const int* in_sizes, int n_in,
                              void* d_out, int out_size)
{
    const float* x     = (const float*)d_in[0];
    const float* w_qkv = (const float*)d_in[2];
    const float* w_out = (const float*)d_in[3];
    float* out = (float*)d_out;

    float *qkv, *attn, *xp, *wqkvp, *woutp;
    cudaGetSymbolAddress((void**)&qkv,   g_qkv);
    cudaGetSymbolAddress((void**)&attn,  g_attn);
    cudaGetSymbolAddress((void**)&xp,    g_xp);
    cudaGetSymbolAddress((void**)&wqkvp, g_wqkvp);
    cudaGetSymbolAddress((void**)&woutp, g_woutp);

    cudaFuncSetAttribute(gemm_mma, cudaFuncAttributeMaxDynamicSharedMemorySize,
                         GEMM_SMEM_BYTES);
    cudaFuncSetAttribute(attn_mma_kernel, cudaFuncAttributeMaxDynamicSharedMemorySize,
                         ATT_SMEM);

    // 0) permute + rna-round GEMM operands
    {
        int n8x = TT * DM / 8;
        perm_round_kernel<<<(n8x + 255) / 256, 256>>>((const float4*)x, (float4*)xp, n8x);
        int n8q = QKV_N * DM / 8;
        perm_round_kernel<<<(n8q + 255) / 256, 256>>>((const float4*)w_qkv, (float4*)wqkvp, n8q);
        int n8o = DM * DM / 8;
        perm_round_kernel<<<(n8o + 255) / 256, 256>>>((const float4*)w_out, (float4*)woutp, n8o);
    }

    // 1) QKV projection + fused RoPE/clamp epilogue
    {
        dim3 grid(QKV_N / 128, TT / 128);
        gemm_mma<<<grid, 128, GEMM_SMEM_BYTES>>>(xp, wqkvp, qkv, QKV_N, DM, 1);
    }

    // 2) Tensor-core flash attention (writes permuted + rounded)
    {
        dim3 grid(TT / 128, NH);
        attn_mma_kernel<<<grid, 256, ATT_SMEM>>>(attn);
    }

    // 3) Output projection
    {
        dim3 grid(DM / 128, TT / 128);
        gemm_mma<<<grid, 128, GEMM_SMEM_BYTES>>>(attn, woutp, out, DM, DM, 0);
    }
}

// round 9
// speedup vs baseline: 1.2587x; 1.0797x over previous
#include <cuda_runtime.h>
#include <cuda_bf16.h>
#include <math.h>
#include <stdint.h>

// Problem constants
#define TT      2048
#define DM      6144
#define NH      48
#define NKV     8
#define HD      128
#define QKV_N   8192
#define KV_OFF  DM
#define V_OFF   (DM + NKV*HD)
#define REP     (NH / NKV)
#define CLAMP_V 8.0f

// Scratch (static device globals)
__device__ float g_qkv[(size_t)TT * QKV_N];
__device__ float g_attn[(size_t)TT * DM];
__device__ float g_xp[(size_t)TT * DM];
__device__ float g_wqkvp[(size_t)QKV_N * DM];
__device__ float g_woutp[(size_t)DM * DM];

// ===========================================================================
// Helpers
// ===========================================================================
__device__ __forceinline__ uint32_t smem_to_u32(const void* p) {
    uint32_t a;
    asm("{ .reg .u64 t; cvta.to.shared.u64 t, %1; cvt.u32.u64 %0, t; }"
        : "=r"(a) : "l"(p));
    return a;
}
__device__ __forceinline__ void cp16(uint32_t s, const void* g) {
    asm volatile("cp.async.cg.shared.global [%0], [%1], 16;"
                 :: "r"(s), "l"(g) : "memory");
}
__device__ __forceinline__ float ftf32(float x) {
    uint32_t o, i = __float_as_uint(x);
    asm("cvt.rna.tf32.f32 %0, %1;" : "=r"(o) : "r"(i));
    return __uint_as_float(o);
}
__device__ __forceinline__ void mma8(float* d, const uint32_t* a, const uint32_t* b) {
    asm volatile(
        "mma.sync.aligned.m16n8k8.row.col.f32.tf32.tf32.f32 "
        "{%0,%1,%2,%3}, {%4,%5,%6,%7}, {%8,%9}, {%0,%1,%2,%3};"
        : "+f"(d[0]), "+f"(d[1]), "+f"(d[2]), "+f"(d[3])
        : "r"(a[0]), "r"(a[1]), "r"(a[2]), "r"(a[3]), "r"(b[0]), "r"(b[1]));
}
__device__ __forceinline__ void mma16bf(float* d, const uint32_t* a, const uint32_t* b) {
    asm volatile(
        "mma.sync.aligned.m16n8k16.row.col.f32.bf16.bf16.f32 "
        "{%0,%1,%2,%3}, {%4,%5,%6,%7}, {%8,%9}, {%0,%1,%2,%3};"
        : "+f"(d[0]), "+f"(d[1]), "+f"(d[2]), "+f"(d[3])
        : "r"(a[0]), "r"(a[1]), "r"(a[2]), "r"(a[3]), "r"(b[0]), "r"(b[1]));
}
__device__ __forceinline__ uint32_t packsplit(float x, float y, uint32_t& lo) {
    __nv_bfloat16 hx = __float2bfloat16(x);
    __nv_bfloat16 hy = __float2bfloat16(y);
    float rx = x - __bfloat162float(hx);
    float ry = y - __bfloat162float(hy);
    __nv_bfloat16 lx = __float2bfloat16(rx);
    __nv_bfloat16 ly = __float2bfloat16(ry);
    lo = ((uint32_t)__bfloat16_as_ushort(ly) << 16) | __bfloat16_as_ushort(lx);
    return ((uint32_t)__bfloat16_as_ushort(hy) << 16) | __bfloat16_as_ushort(hx);
}
__device__ __forceinline__ float clmp(float v) {
    return fminf(fmaxf(v, -CLAMP_V), CLAMP_V);
}

// ===========================================================================
// Permute (within-8 interleave [0,4,1,5,2,6,3,7]) + rna-tf32 round.
// ===========================================================================
__global__ __launch_bounds__(256)
void perm_round_kernel(const float4* __restrict__ src, float4* __restrict__ dst, int n8)
{
    int g = blockIdx.x * blockDim.x + threadIdx.x;
    if (g < n8) {
        float4 i0 = src[2 * g];
        float4 i1 = src[2 * g + 1];
        float4 o0 = make_float4(ftf32(i0.x), ftf32(i1.x), ftf32(i0.y), ftf32(i1.y));
        float4 o1 = make_float4(ftf32(i0.z), ftf32(i1.z), ftf32(i0.w), ftf32(i1.w));
        dst[2 * g]     = o0;
        dst[2 * g + 1] = o1;
    }
}

// ===========================================================================
// tf32 mma.sync GEMM on K-PERMUTED pre-rounded operands.
// CTA tile 128x128, 256 threads (8 warps, warp tile 64x32) -- R6 shape.
// 3-stage cp.async pipeline, ONE __syncthreads per iter.
// SMEM: unpadded 128B rows with XOR swizzle u' = u ^ ((row&3)<<1) at float4
// granularity -> conflict-free for both the cp.async writes and the
// float2 fragment reads (8B-group index = 4*(ks^(gr&3)) + tc, bijective
// over each 16-lane phase).  mode 1: fused RoPE+clamp epilogue.
// ===========================================================================
#define TSZ  (128 * 32)                       // floats per operand per stage (16KB)
#define GEMM_SMEM_BYTES (6 * TSZ * 4)         // 3 stages x 2 operands = 98304

__global__ __launch_bounds__(256, 2)
void gemm_mma(const float* __restrict__ A, const float* __restrict__ B,
              float* __restrict__ C, int N, int K, int mode)
{
    extern __shared__ float sm[];
    const int tid  = threadIdx.x;
    const int wid  = tid >> 5, lane = tid & 31;
    const int wm   = (wid >> 2) * 64;       // 0 / 64
    const int wn   = (wid & 3) * 32;        // 0 / 32 / 64 / 96
    const int gr   = lane >> 2, tc = lane & 3;
    const int bm   = blockIdx.y * 128, bn = blockIdx.x * 128;

    const int ldr = tid >> 3;               // 0..31
    const int ldu = tid & 7;                // float4 unit 0..7

    const uint32_t sbase = smem_to_u32(sm);
    const int NS = K / 32;

    float acc[4][4][4];
#pragma unroll
    for (int i = 0; i < 4; i++)
#pragma unroll
        for (int j = 0; j < 4; j++)
#pragma unroll
            for (int r = 0; r < 4; r++) acc[i][j][r] = 0.f;

    // swizzled float4 unit for the loader (row&3 is constant across v)
    const int lsw = (ldr & 3) << 1;
    const int lu  = (ldu ^ lsw) << 2;       // float offset within row

    auto loadTiles = [&](int k0, int st) {
#pragma unroll
        for (int v = 0; v < 4; v++) {
            int row = ldr + v * 32;
            uint32_t sa = sbase + (uint32_t)(st * TSZ + row * 32 + lu) * 4;
            cp16(sa, A + (size_t)(bm + row) * K + k0 + ldu * 4);
            uint32_t sb = sbase + (uint32_t)(3 * TSZ + st * TSZ + row * 32 + lu) * 4;
            cp16(sb, B + (size_t)(bn + row) * K + k0 + ldu * 4);
        }
        asm volatile("cp.async.commit_group;" ::: "memory");
    };

    loadTiles(0, 0);
    loadTiles(32, 1);

    const int asw = (gr & 3) << 1;          // fragment-read swizzle (row&3 == gr&3)
    const int ain = 2 * (tc & 1);           // inner float2 offset

    int st = 0;
    for (int s = 0; s < NS; s++) {
        asm volatile("cp.async.wait_group 1;" ::: "memory");
        __syncthreads();

        int nst = st + 2; if (nst >= 3) nst -= 3;
        if (s + 2 < NS) loadTiles((s + 2) * 32, nst);
        else asm volatile("cp.async.commit_group;" ::: "memory");

        const float* As_ = sm + st * TSZ;
        const float* Bs_ = sm + 3 * TSZ + st * TSZ;

#pragma unroll
        for (int ks = 0; ks < 4; ks++) {
            const int u   = 2 * ks + (tc >> 1);
            const int uof = ((u ^ asw) << 2) + ain;   // swizzled float offset in row
            uint32_t a[4][4], b[4][2];
#pragma unroll
            for (int i = 0; i < 4; i++) {
                int r0 = wm + i * 16 + gr;
                float2 alo = *(const float2*)(As_ + r0 * 32 + uof);
                float2 ahi = *(const float2*)(As_ + (r0 + 8) * 32 + uof);
                a[i][0] = __float_as_uint(alo.x);
                a[i][1] = __float_as_uint(ahi.x);
                a[i][2] = __float_as_uint(alo.y);
                a[i][3] = __float_as_uint(ahi.y);
            }
#pragma unroll
            for (int j = 0; j < 4; j++) {
                int r0 = wn + j * 8 + gr;
                float2 bv = *(const float2*)(Bs_ + r0 * 32 + uof);
                b[j][0] = __float_as_uint(bv.x);
                b[j][1] = __float_as_uint(bv.y);
            }
#pragma unroll
            for (int i = 0; i < 4; i++)
#pragma unroll
                for (int j = 0; j < 4; j++)
                    mma8(acc[i][j], a[i], b[j]);
        }

        if (++st == 3) st = 0;
    }

    // Epilogue (pairs (c, c+1) per float2 == RoPE pairs when mode==1)
#pragma unroll
    for (int i = 0; i < 4; i++) {
#pragma unroll
        for (int j = 0; j < 4; j++) {
            int r = bm + wm + i * 16 + gr;
            int c = bn + wn + j * 8 + tc * 2;
            float2 v0 = make_float2(acc[i][j][0], acc[i][j][1]);
            float2 v1 = make_float2(acc[i][j][2], acc[i][j][3]);
            if (mode == 1) {
                if (c < V_OFF) {
                    int i64 = (c >> 1) & 63;
                    float inv = (float)pow(500000.0, -(double)i64 / 64.0);
                    float s0, c0;
                    sincosf((float)r * inv, &s0, &c0);
                    float a0 = v0.x, b0 = v0.y;
                    v0.x = clmp(a0 * c0 - b0 * s0);
                    v0.y = clmp(a0 * s0 + b0 * c0);
                    float s1, c1;
                    sincosf((float)(r + 8) * inv, &s1, &c1);
                    float a1 = v1.x, b1 = v1.y;
                    v1.x = clmp(a1 * c1 - b1 * s1);
                    v1.y = clmp(a1 * s1 + b1 * c1);
                } else {
                    v0.x = clmp(v0.x); v0.y = clmp(v0.y);
                    v1.x = clmp(v1.x); v1.y = clmp(v1.y);
                }
            }
            *(float2*)&C[(size_t)r * N + c]       = v0;
            *(float2*)&C[(size_t)(r + 8) * N + c] = v1;
        }
    }
}

// ===========================================================================
// Tensor-core flash attention (unchanged; writes permuted + rounded).
// ===========================================================================
#define A_QH   0
#define A_QL   34816
#define A_KH   69632
#define A_KL   87040
#define A_VT   104448
#define A_VS   139264
#define A_PH   139264
#define A_SS   174080
#define A_PL   174080
#define A_STAT 208896
#define ATT_SMEM 210432

__global__ __launch_bounds__(256, 1)
void attn_mma_kernel(float* __restrict__ out)
{
    extern __shared__ char smem[];
    uint32_t* QHw = (uint32_t*)(smem + A_QH);
    uint32_t* QLw = (uint32_t*)(smem + A_QL);
    uint32_t* KHw = (uint32_t*)(smem + A_KH);
    uint32_t* KLw = (uint32_t*)(smem + A_KL);
    float*    VT  = (float*)(smem + A_VT);
    float*    VS  = (float*)(smem + A_VS);
    float*    PH  = (float*)(smem + A_PH);
    float*    SS  = (float*)(smem + A_SS);
    float*    PL  = SS;
    float* rowM = (float*)(smem + A_STAT);
    float* rowL = rowM + 128;
    float* rowA = rowL + 128;

    const int qb   = gridDim.x - 1 - blockIdx.x;
    const int h    = blockIdx.y;
    const int kh   = h / REP;
    const int tid  = threadIdx.x;
    const int wid  = tid >> 5, lane = tid & 31;
    const int gr   = lane >> 2, tc = lane & 3;
    const int m0   = (wid >> 1) * 32;
    const int wn   = (wid & 1) * 32;
    const int nv   = (wid & 1) * 64;
    const float scale = 0.088388347648318447f;

    {
        const float* qg = g_qkv + (size_t)(qb * 128) * QKV_N + h * HD;
#pragma unroll
        for (int i = 0; i < 16; i++) {
            int f = tid + i * 256;
            int r = f >> 5;
            int c = (f & 31) * 4;
            float4 v = *(const float4*)(qg + (size_t)r * QKV_N + c);
            uint32_t l0, l1;
            uint32_t h0 = packsplit(v.x, v.y, l0);
            uint32_t h1 = packsplit(v.z, v.w, l1);
            QHw[r * 68 + c / 2]     = h0;
            QHw[r * 68 + c / 2 + 1] = h1;
            QLw[r * 68 + c / 2]     = l0;
            QLw[r * 68 + c / 2 + 1] = l1;
        }
    }
    if (tid < 128) { rowM[tid] = -1e30f; rowL[tid] = 0.f; }

    float o[2][8][4];
#pragma unroll
    for (int mi = 0; mi < 2; mi++)
#pragma unroll
        for (int j = 0; j < 8; j++)
#pragma unroll
            for (int r = 0; r < 4; r++) o[mi][j][r] = 0.f;

    const int nkt = 2 * qb + 2;
    for (int kt = 0; kt < nkt; kt++) {
        __syncthreads();

        {
            const float* kg = g_qkv + (size_t)(kt * 64) * QKV_N + KV_OFF + kh * HD;
            const float* vg = g_qkv + (size_t)(kt * 64) * QKV_N + V_OFF  + kh * HD;
#pragma unroll
            for (int i = 0; i < 8; i++) {
                int f = tid + i * 256;
                int r = f >> 5;
                int c = (f & 31) * 4;
                float4 kv = *(const float4*)(kg + (size_t)r * QKV_N + c);
                uint32_t l0, l1;
                uint32_t h0 = packsplit(kv.x, kv.y, l0);
                uint32_t h1 = packsplit(kv.z, kv.w, l1);
                KHw[r * 68 + c / 2]     = h0;
                KHw[r * 68 + c / 2 + 1] = h1;
                KLw[r * 68 + c / 2]     = l0;
                KLw[r * 68 + c / 2 + 1] = l1;
                float4 vv = *(const float4*)(vg + (size_t)r * QKV_N + c);
                VS[r * 133 + c + 0] = vv.x;
                VS[r * 133 + c + 1] = vv.y;
                VS[r * 133 + c + 2] = vv.z;
                VS[r * 133 + c + 3] = vv.w;
            }
        }
        __syncthreads();

#pragma unroll
        for (int i = 0; i < 32; i++) {
            int widx = wid + 8 * i;
            int d = widx >> 1;
            int r = (widx & 1) * 32 + lane;
            VT[d * 68 + r] = ftf32(VS[r * 133 + d]);
        }

        float sacc[2][4][4];
#pragma unroll
        for (int mi = 0; mi < 2; mi++)
#pragma unroll
            for (int j = 0; j < 4; j++)
#pragma unroll
                for (int r = 0; r < 4; r++) sacc[mi][j][r] = 0.f;

#pragma unroll
        for (int ks = 0; ks < 8; ks++) {
            uint32_t ah[2][4], al[2][4];
#pragma unroll
            for (int mi = 0; mi < 2; mi++) {
                int base = (m0 + mi * 16 + gr) * 68 + ks * 8 + tc;
                ah[mi][0] = QHw[base];
                ah[mi][1] = QHw[base + 8 * 68];
                ah[mi][2] = QHw[base + 4];
                ah[mi][3] = QHw[base + 8 * 68 + 4];
                al[mi][0] = QLw[base];
                al[mi][1] = QLw[base + 8 * 68];
                al[mi][2] = QLw[base + 4];
                al[mi][3] = QLw[base + 8 * 68 + 4];
            }
            uint32_t bh[4][2], bl[4][2];
#pragma unroll
            for (int j = 0; j < 4; j++) {
                int base = (wn + j * 8 + gr) * 68 + ks * 8 + tc;
                bh[j][0] = KHw[base];
                bh[j][1] = KHw[base + 4];
                bl[j][0] = KLw[base];
                bl[j][1] = KLw[base + 4];
            }
#pragma unroll
            for (int mi = 0; mi < 2; mi++)
#pragma unroll
                for (int j = 0; j < 4; j++) {
                    mma16bf(sacc[mi][j], ah[mi], bh[j]);
                    mma16bf(sacc[mi][j], ah[mi], bl[j]);
                    mma16bf(sacc[mi][j], al[mi], bh[j]);
                }
        }

        const bool dg = (kt >= 2 * qb);
#pragma unroll
        for (int mi = 0; mi < 2; mi++) {
#pragma unroll
            for (int j = 0; j < 4; j++) {
                int rl0 = m0 + mi * 16 + gr;
                int cl  = wn + j * 8 + 2 * tc;
                float v0 = sacc[mi][j][0] * scale;
                float v1 = sacc[mi][j][1] * scale;
                float v2 = sacc[mi][j][2] * scale;
                float v3 = sacc[mi][j][3] * scale;
                if (dg) {
                    int rg0 = qb * 128 + rl0;
                    int cg  = kt * 64 + cl;
                    if (cg     > rg0)     v0 = -1e30f;
                    if (cg + 1 > rg0)     v1 = -1e30f;
                    if (cg     > rg0 + 8) v2 = -1e30f;
                    if (cg + 1 > rg0 + 8) v3 = -1e30f;
                }
                *(float2*)&SS[rl0 * 68 + cl]       = make_float2(v0, v1);
                *(float2*)&SS[(rl0 + 8) * 68 + cl] = make_float2(v2, v3);
            }
        }
        __syncthreads();

        if (tid < 128) {
            int r = tid;
            float mOld = rowM[r];
            float m = mOld;
            const float4* srow = (const float4*)(SS + r * 68);
#pragma unroll
            for (int jj = 0; jj < 16; jj++) {
                float4 s4 = srow[jj];
                m = fmaxf(m, fmaxf(fmaxf(s4.x, s4.y), fmaxf(s4.z, s4.w)));
            }
            float alpha = __expf(mOld - m);
            float l = 0.f;
#pragma unroll
            for (int jj = 0; jj < 16; jj++) {
                float4 s4 = srow[jj];
                float p0 = __expf(s4.x - m);
                float p1 = __expf(s4.y - m);
                float p2 = __expf(s4.z - m);
                float p3 = __expf(s4.w - m);
                l += (p0 + p1) + (p2 + p3);
                float h0 = ftf32(p0), h1 = ftf32(p1), h2 = ftf32(p2), h3 = ftf32(p3);
                float4 hv = make_float4(h0, h1, h2, h3);
                float4 lv = make_float4(ftf32(p0 - h0), ftf32(p1 - h1),
                                        ftf32(p2 - h2), ftf32(p3 - h3));
                *(float4*)&PH[r * 68 + jj * 4] = hv;
                *(float4*)&PL[r * 68 + jj * 4] = lv;
            }
            rowL[r] = rowL[r] * alpha + l;
            rowM[r] = m;
            rowA[r] = alpha;
        }
        __syncthreads();

#pragma unroll
        for (int mi = 0; mi < 2; mi++) {
            float am0 = rowA[m0 + mi * 16 + gr];
            float am1 = rowA[m0 + mi * 16 + gr + 8];
#pragma unroll
            for (int j = 0; j < 8; j++) {
                o[mi][j][0] *= am0; o[mi][j][1] *= am0;
                o[mi][j][2] *= am1; o[mi][j][3] *= am1;
            }
        }
#pragma unroll
        for (int ks = 0; ks < 8; ks++) {
            uint32_t ap[2][4], alr[2][4];
#pragma unroll
            for (int mi = 0; mi < 2; mi++) {
                int base = (m0 + mi * 16 + gr) * 68 + ks * 8 + tc;
                ap[mi][0]  = __float_as_uint(PH[base]);
                ap[mi][1]  = __float_as_uint(PH[base + 8 * 68]);
                ap[mi][2]  = __float_as_uint(PH[base + 4]);
                ap[mi][3]  = __float_as_uint(PH[base + 8 * 68 + 4]);
                alr[mi][0] = __float_as_uint(PL[base]);
                alr[mi][1] = __float_as_uint(PL[base + 8 * 68]);
                alr[mi][2] = __float_as_uint(PL[base + 4]);
                alr[mi][3] = __float_as_uint(PL[base + 8 * 68 + 4]);
            }
#pragma unroll
            for (int j = 0; j < 8; j++) {
                int base = (nv + j * 8 + gr) * 68 + ks * 8 + tc;
                uint32_t b[2];
                b[0] = __float_as_uint(VT[base]);
                b[1] = __float_as_uint(VT[base + 4]);
#pragma unroll
                for (int mi = 0; mi < 2; mi++) {
                    mma8(o[mi][j], ap[mi], b);
                    mma8(o[mi][j], alr[mi], b);
                }
            }
        }
    }

    // normalize + rna-round + K-PERMUTED store
    const int p0 = (tc < 2) ? 4 * tc     : 4 * tc - 7;
    const int p1 = (tc < 2) ? 4 * tc + 2 : 4 * tc - 5;
#pragma unroll
    for (int mi = 0; mi < 2; mi++) {
        int rl0 = m0 + mi * 16 + gr;
        float inv0 = 1.f / rowL[rl0];
        float inv1 = 1.f / rowL[rl0 + 8];
        int rg0 = qb * 128 + rl0;
#pragma unroll
        for (int j = 0; j < 8; j++) {
            int gbase = h * HD + nv + j * 8;
            float* d0 = out + (size_t)rg0 * DM + gbase;
            float* d1 = out + (size_t)(rg0 + 8) * DM + gbase;
            d0[p0] = ftf32(o[mi][j][0] * inv0);
            d0[p1] = ftf32(o[mi][j][1] * inv0);
            d1[p0] = ftf32(o[mi][j][2] * inv1);
            d1[p1] = ftf32(o[mi][j][3] * inv1);
        }
    }
}

// ===========================================================================
// Host side
// ===========================================================================
extern "C" void kernel_launch(void* const* d_in, const int* in_sizes, int n_in,
                              void* d_out, int out_size)
{
    const float* x     = (const float*)d_in[0];
    const float* w_qkv = (const float*)d_in[2];
    const float* w_out = (const float*)d_in[3];
    float* out = (float*)d_out;

    float *qkv, *attn, *xp, *wqkvp, *woutp;
    cudaGetSymbolAddress((void**)&qkv,   g_qkv);
    cudaGetSymbolAddress((void**)&attn,  g_attn);
    cudaGetSymbolAddress((void**)&xp,    g_xp);
    cudaGetSymbolAddress((void**)&wqkvp, g_wqkvp);
    cudaGetSymbolAddress((void**)&woutp, g_woutp);

    cudaFuncSetAttribute(gemm_mma, cudaFuncAttributeMaxDynamicSharedMemorySize,
                         GEMM_SMEM_BYTES);
    cudaFuncSetAttribute(attn_mma_kernel, cudaFuncAttributeMaxDynamicSharedMemorySize,
                         ATT_SMEM);

    // 0) permute + rna-round GEMM operands
    {
        int n8x = TT * DM / 8;
        perm_round_kernel<<<(n8x + 255) / 256, 256>>>((const float4*)x, (float4*)xp, n8x);
        int n8q = QKV_N * DM / 8;
        perm_round_kernel<<<(n8q + 255) / 256, 256>>>((const float4*)w_qkv, (float4*)wqkvp, n8q);
        int n8o = DM * DM / 8;
        perm_round_kernel<<<(n8o + 255) / 256, 256>>>((const float4*)w_out, (float4*)woutp, n8o);
    }

    // 1) QKV projection + fused RoPE/clamp epilogue
    {
        dim3 grid(QKV_N / 128, TT / 128);
        gemm_mma<<<grid, 256, GEMM_SMEM_BYTES>>>(xp, wqkvp, qkv, QKV_N, DM, 1);
    }

    // 2) Tensor-core flash attention (writes permuted + rounded)
    {
        dim3 grid(TT / 128, NH);
        attn_mma_kernel<<<grid, 256, ATT_SMEM>>>(attn);
    }

    // 3) Output projection
    {
        dim3 grid(DM / 128, TT / 128);
        gemm_mma<<<grid, 256, GEMM_SMEM_BYTES>>>(attn, woutp, out, DM, DM, 0);
    }
}

// round 10
// speedup vs baseline: 1.2726x; 1.0110x over previous
#include <cuda_runtime.h>
#include <cuda_bf16.h>
#include <math.h>
#include <stdint.h>

// Problem constants
#define TT      2048
#define DM      6144
#define NH      48
#define NKV     8
#define HD      128
#define QKV_N   8192
#define KV_OFF  DM
#define V_OFF   (DM + NKV*HD)
#define REP     (NH / NKV)
#define CLAMP_V 8.0f

// Scratch (static device globals)
__device__ float g_qkv[(size_t)TT * QKV_N];
__device__ float g_attn[(size_t)TT * DM];
__device__ float g_xp[(size_t)TT * DM];
__device__ float g_wqkvp[(size_t)QKV_N * DM];
__device__ float g_woutp[(size_t)DM * DM];

// ===========================================================================
// Helpers
// ===========================================================================
__device__ __forceinline__ uint32_t smem_to_u32(const void* p) {
    uint32_t a;
    asm("{ .reg .u64 t; cvta.to.shared.u64 t, %1; cvt.u32.u64 %0, t; }"
        : "=r"(a) : "l"(p));
    return a;
}
__device__ __forceinline__ void cp16(uint32_t s, const void* g) {
    asm volatile("cp.async.cg.shared.global [%0], [%1], 16;"
                 :: "r"(s), "l"(g) : "memory");
}
__device__ __forceinline__ float ftf32(float x) {
    uint32_t o, i = __float_as_uint(x);
    asm("cvt.rna.tf32.f32 %0, %1;" : "=r"(o) : "r"(i));
    return __uint_as_float(o);
}
__device__ __forceinline__ void mma8(float* d, const uint32_t* a, const uint32_t* b) {
    asm volatile(
        "mma.sync.aligned.m16n8k8.row.col.f32.tf32.tf32.f32 "
        "{%0,%1,%2,%3}, {%4,%5,%6,%7}, {%8,%9}, {%0,%1,%2,%3};"
        : "+f"(d[0]), "+f"(d[1]), "+f"(d[2]), "+f"(d[3])
        : "r"(a[0]), "r"(a[1]), "r"(a[2]), "r"(a[3]), "r"(b[0]), "r"(b[1]));
}
__device__ __forceinline__ void mma16bf(float* d, const uint32_t* a, const uint32_t* b) {
    asm volatile(
        "mma.sync.aligned.m16n8k16.row.col.f32.bf16.bf16.f32 "
        "{%0,%1,%2,%3}, {%4,%5,%6,%7}, {%8,%9}, {%0,%1,%2,%3};"
        : "+f"(d[0]), "+f"(d[1]), "+f"(d[2]), "+f"(d[3])
        : "r"(a[0]), "r"(a[1]), "r"(a[2]), "r"(a[3]), "r"(b[0]), "r"(b[1]));
}
__device__ __forceinline__ uint32_t packsplit(float x, float y, uint32_t& lo) {
    __nv_bfloat16 hx = __float2bfloat16(x);
    __nv_bfloat16 hy = __float2bfloat16(y);
    float rx = x - __bfloat162float(hx);
    float ry = y - __bfloat162float(hy);
    __nv_bfloat16 lx = __float2bfloat16(rx);
    __nv_bfloat16 ly = __float2bfloat16(ry);
    lo = ((uint32_t)__bfloat16_as_ushort(ly) << 16) | __bfloat16_as_ushort(lx);
    return ((uint32_t)__bfloat16_as_ushort(hy) << 16) | __bfloat16_as_ushort(hx);
}
__device__ __forceinline__ float clmp(float v) {
    return fminf(fmaxf(v, -CLAMP_V), CLAMP_V);
}

// ===========================================================================
// Permute (within-8 interleave [0,4,1,5,2,6,3,7]) + rna-tf32 round.
// ===========================================================================
__global__ __launch_bounds__(256)
void perm_round_kernel(const float4* __restrict__ src, float4* __restrict__ dst, int n8)
{
    int g = blockIdx.x * blockDim.x + threadIdx.x;
    if (g < n8) {
        float4 i0 = src[2 * g];
        float4 i1 = src[2 * g + 1];
        float4 o0 = make_float4(ftf32(i0.x), ftf32(i1.x), ftf32(i0.y), ftf32(i1.y));
        float4 o1 = make_float4(ftf32(i0.z), ftf32(i1.z), ftf32(i0.w), ftf32(i1.w));
        dst[2 * g]     = o0;
        dst[2 * g + 1] = o1;
    }
}

// ===========================================================================
// tf32 mma.sync GEMM on K-PERMUTED pre-rounded operands.
// CTA tile 128x128, 256 threads (8 warps, warp tile 64x32), 2 CTAs/SM.
// 3-stage cp.async pipeline, ONE __syncthreads per iter. XOR-swizzled SMEM.
// R10: all loop-invariant address math hoisted (uofs[4], arow[4], brow[4]).
// mode 1: fused RoPE+clamp epilogue.
// ===========================================================================
#define TSZ  (128 * 32)                       // floats per operand per stage (16KB)
#define GEMM_SMEM_BYTES (6 * TSZ * 4)         // 3 stages x 2 operands = 98304

__global__ __launch_bounds__(256, 2)
void gemm_mma(const float* __restrict__ A, const float* __restrict__ B,
              float* __restrict__ C, int N, int K, int mode)
{
    extern __shared__ float sm[];
    const int tid  = threadIdx.x;
    const int wid  = tid >> 5, lane = tid & 31;
    const int wm   = (wid >> 2) * 64;       // 0 / 64
    const int wn   = (wid & 3) * 32;        // 0 / 32 / 64 / 96
    const int gr   = lane >> 2, tc = lane & 3;
    const int bm   = blockIdx.y * 128, bn = blockIdx.x * 128;

    const int ldr = tid >> 3;               // 0..31
    const int ldu = tid & 7;                // float4 unit 0..7

    const uint32_t sbase = smem_to_u32(sm);
    const int NS = K / 32;

    float acc[4][4][4];
#pragma unroll
    for (int i = 0; i < 4; i++)
#pragma unroll
        for (int j = 0; j < 4; j++)
#pragma unroll
            for (int r = 0; r < 4; r++) acc[i][j][r] = 0.f;

    // swizzled float4 unit for the loader (row&3 is constant across v)
    const int lsw = (ldr & 3) << 1;
    const int lu  = (ldu ^ lsw) << 2;       // float offset within row

    auto loadTiles = [&](int k0, int st) {
#pragma unroll
        for (int v = 0; v < 4; v++) {
            int row = ldr + v * 32;
            uint32_t sa = sbase + (uint32_t)(st * TSZ + row * 32 + lu) * 4;
            cp16(sa, A + (size_t)(bm + row) * K + k0 + ldu * 4);
            uint32_t sb = sbase + (uint32_t)(3 * TSZ + st * TSZ + row * 32 + lu) * 4;
            cp16(sb, B + (size_t)(bn + row) * K + k0 + ldu * 4);
        }
        asm volatile("cp.async.commit_group;" ::: "memory");
    };

    loadTiles(0, 0);
    loadTiles(32, 1);

    // ---- Hoisted loop-invariant address components ----
    const int asw = (gr & 3) << 1;
    const int ain = 2 * (tc & 1);
    int uofs[4];
#pragma unroll
    for (int ks = 0; ks < 4; ks++) {
        int u = 2 * ks + (tc >> 1);
        uofs[ks] = ((u ^ asw) << 2) + ain;  // swizzled float offset within row
    }
    int arow[4], brow[4];
#pragma unroll
    for (int i = 0; i < 4; i++) arow[i] = (wm + i * 16 + gr) * 32;
#pragma unroll
    for (int j = 0; j < 4; j++) brow[j] = (wn + j * 8 + gr) * 32;

    int st = 0;
    for (int s = 0; s < NS; s++) {
        asm volatile("cp.async.wait_group 1;" ::: "memory");
        __syncthreads();

        int nst = st + 2; if (nst >= 3) nst -= 3;
        if (s + 2 < NS) loadTiles((s + 2) * 32, nst);
        else asm volatile("cp.async.commit_group;" ::: "memory");

        const float* As_ = sm + st * TSZ;
        const float* Bs_ = sm + 3 * TSZ + st * TSZ;

#pragma unroll
        for (int ks = 0; ks < 4; ks++) {
            const int uof = uofs[ks];
            uint32_t a[4][4], b[4][2];
#pragma unroll
            for (int i = 0; i < 4; i++) {
                const float* ap = As_ + arow[i] + uof;
                float2 alo = *(const float2*)(ap);
                float2 ahi = *(const float2*)(ap + 256);     // +8 rows * 32
                a[i][0] = __float_as_uint(alo.x);
                a[i][1] = __float_as_uint(ahi.x);
                a[i][2] = __float_as_uint(alo.y);
                a[i][3] = __float_as_uint(ahi.y);
            }
#pragma unroll
            for (int j = 0; j < 4; j++) {
                float2 bv = *(const float2*)(Bs_ + brow[j] + uof);
                b[j][0] = __float_as_uint(bv.x);
                b[j][1] = __float_as_uint(bv.y);
            }
#pragma unroll
            for (int i = 0; i < 4; i++)
#pragma unroll
                for (int j = 0; j < 4; j++)
                    mma8(acc[i][j], a[i], b[j]);
        }

        if (++st == 3) st = 0;
    }

    // Epilogue (pairs (c, c+1) per float2 == RoPE pairs when mode==1)
#pragma unroll
    for (int i = 0; i < 4; i++) {
#pragma unroll
        for (int j = 0; j < 4; j++) {
            int r = bm + wm + i * 16 + gr;
            int c = bn + wn + j * 8 + tc * 2;
            float2 v0 = make_float2(acc[i][j][0], acc[i][j][1]);
            float2 v1 = make_float2(acc[i][j][2], acc[i][j][3]);
            if (mode == 1) {
                if (c < V_OFF) {
                    int i64 = (c >> 1) & 63;
                    float inv = (float)pow(500000.0, -(double)i64 / 64.0);
                    float s0, c0;
                    sincosf((float)r * inv, &s0, &c0);
                    float a0 = v0.x, b0 = v0.y;
                    v0.x = clmp(a0 * c0 - b0 * s0);
                    v0.y = clmp(a0 * s0 + b0 * c0);
                    float s1, c1;
                    sincosf((float)(r + 8) * inv, &s1, &c1);
                    float a1 = v1.x, b1 = v1.y;
                    v1.x = clmp(a1 * c1 - b1 * s1);
                    v1.y = clmp(a1 * s1 + b1 * c1);
                } else {
                    v0.x = clmp(v0.x); v0.y = clmp(v0.y);
                    v1.x = clmp(v1.x); v1.y = clmp(v1.y);
                }
            }
            *(float2*)&C[(size_t)r * N + c]       = v0;
            *(float2*)&C[(size_t)(r + 8) * N + c] = v1;
        }
    }
}

// ===========================================================================
// Tensor-core flash attention (unchanged; writes permuted + rounded).
// ===========================================================================
#define A_QH   0
#define A_QL   34816
#define A_KH   69632
#define A_KL   87040
#define A_VT   104448
#define A_VS   139264
#define A_PH   139264
#define A_SS   174080
#define A_PL   174080
#define A_STAT 208896
#define ATT_SMEM 210432

__global__ __launch_bounds__(256, 1)
void attn_mma_kernel(float* __restrict__ out)
{
    extern __shared__ char smem[];
    uint32_t* QHw = (uint32_t*)(smem + A_QH);
    uint32_t* QLw = (uint32_t*)(smem + A_QL);
    uint32_t* KHw = (uint32_t*)(smem + A_KH);
    uint32_t* KLw = (uint32_t*)(smem + A_KL);
    float*    VT  = (float*)(smem + A_VT);
    float*    VS  = (float*)(smem + A_VS);
    float*    PH  = (float*)(smem + A_PH);
    float*    SS  = (float*)(smem + A_SS);
    float*    PL  = SS;
    float* rowM = (float*)(smem + A_STAT);
    float* rowL = rowM + 128;
    float* rowA = rowL + 128;

    const int qb   = gridDim.x - 1 - blockIdx.x;
    const int h    = blockIdx.y;
    const int kh   = h / REP;
    const int tid  = threadIdx.x;
    const int wid  = tid >> 5, lane = tid & 31;
    const int gr   = lane >> 2, tc = lane & 3;
    const int m0   = (wid >> 1) * 32;
    const int wn   = (wid & 1) * 32;
    const int nv   = (wid & 1) * 64;
    const float scale = 0.088388347648318447f;

    {
        const float* qg = g_qkv + (size_t)(qb * 128) * QKV_N + h * HD;
#pragma unroll
        for (int i = 0; i < 16; i++) {
            int f = tid + i * 256;
            int r = f >> 5;
            int c = (f & 31) * 4;
            float4 v = *(const float4*)(qg + (size_t)r * QKV_N + c);
            uint32_t l0, l1;
            uint32_t h0 = packsplit(v.x, v.y, l0);
            uint32_t h1 = packsplit(v.z, v.w, l1);
            QHw[r * 68 + c / 2]     = h0;
            QHw[r * 68 + c / 2 + 1] = h1;
            QLw[r * 68 + c / 2]     = l0;
            QLw[r * 68 + c / 2 + 1] = l1;
        }
    }
    if (tid < 128) { rowM[tid] = -1e30f; rowL[tid] = 0.f; }

    float o[2][8][4];
#pragma unroll
    for (int mi = 0; mi < 2; mi++)
#pragma unroll
        for (int j = 0; j < 8; j++)
#pragma unroll
            for (int r = 0; r < 4; r++) o[mi][j][r] = 0.f;

    const int nkt = 2 * qb + 2;
    for (int kt = 0; kt < nkt; kt++) {
        __syncthreads();

        {
            const float* kg = g_qkv + (size_t)(kt * 64) * QKV_N + KV_OFF + kh * HD;
            const float* vg = g_qkv + (size_t)(kt * 64) * QKV_N + V_OFF  + kh * HD;
#pragma unroll
            for (int i = 0; i < 8; i++) {
                int f = tid + i * 256;
                int r = f >> 5;
                int c = (f & 31) * 4;
                float4 kv = *(const float4*)(kg + (size_t)r * QKV_N + c);
                uint32_t l0, l1;
                uint32_t h0 = packsplit(kv.x, kv.y, l0);
                uint32_t h1 = packsplit(kv.z, kv.w, l1);
                KHw[r * 68 + c / 2]     = h0;
                KHw[r * 68 + c / 2 + 1] = h1;
                KLw[r * 68 + c / 2]     = l0;
                KLw[r * 68 + c / 2 + 1] = l1;
                float4 vv = *(const float4*)(vg + (size_t)r * QKV_N + c);
                VS[r * 133 + c + 0] = vv.x;
                VS[r * 133 + c + 1] = vv.y;
                VS[r * 133 + c + 2] = vv.z;
                VS[r * 133 + c + 3] = vv.w;
            }
        }
        __syncthreads();

#pragma unroll
        for (int i = 0; i < 32; i++) {
            int widx = wid + 8 * i;
            int d = widx >> 1;
            int r = (widx & 1) * 32 + lane;
            VT[d * 68 + r] = ftf32(VS[r * 133 + d]);
        }

        float sacc[2][4][4];
#pragma unroll
        for (int mi = 0; mi < 2; mi++)
#pragma unroll
            for (int j = 0; j < 4; j++)
#pragma unroll
                for (int r = 0; r < 4; r++) sacc[mi][j][r] = 0.f;

#pragma unroll
        for (int ks = 0; ks < 8; ks++) {
            uint32_t ah[2][4], al[2][4];
#pragma unroll
            for (int mi = 0; mi < 2; mi++) {
                int base = (m0 + mi * 16 + gr) * 68 + ks * 8 + tc;
                ah[mi][0] = QHw[base];
                ah[mi][1] = QHw[base + 8 * 68];
                ah[mi][2] = QHw[base + 4];
                ah[mi][3] = QHw[base + 8 * 68 + 4];
                al[mi][0] = QLw[base];
                al[mi][1] = QLw[base + 8 * 68];
                al[mi][2] = QLw[base + 4];
                al[mi][3] = QLw[base + 8 * 68 + 4];
            }
            uint32_t bh[4][2], bl[4][2];
#pragma unroll
            for (int j = 0; j < 4; j++) {
                int base = (wn + j * 8 + gr) * 68 + ks * 8 + tc;
                bh[j][0] = KHw[base];
                bh[j][1] = KHw[base + 4];
                bl[j][0] = KLw[base];
                bl[j][1] = KLw[base + 4];
            }
#pragma unroll
            for (int mi = 0; mi < 2; mi++)
#pragma unroll
                for (int j = 0; j < 4; j++) {
                    mma16bf(sacc[mi][j], ah[mi], bh[j]);
                    mma16bf(sacc[mi][j], ah[mi], bl[j]);
                    mma16bf(sacc[mi][j], al[mi], bh[j]);
                }
        }

        const bool dg = (kt >= 2 * qb);
#pragma unroll
        for (int mi = 0; mi < 2; mi++) {
#pragma unroll
            for (int j = 0; j < 4; j++) {
                int rl0 = m0 + mi * 16 + gr;
                int cl  = wn + j * 8 + 2 * tc;
                float v0 = sacc[mi][j][0] * scale;
                float v1 = sacc[mi][j][1] * scale;
                float v2 = sacc[mi][j][2] * scale;
                float v3 = sacc[mi][j][3] * scale;
                if (dg) {
                    int rg0 = qb * 128 + rl0;
                    int cg  = kt * 64 + cl;
                    if (cg     > rg0)     v0 = -1e30f;
                    if (cg + 1 > rg0)     v1 = -1e30f;
                    if (cg     > rg0 + 8) v2 = -1e30f;
                    if (cg + 1 > rg0 + 8) v3 = -1e30f;
                }
                *(float2*)&SS[rl0 * 68 + cl]       = make_float2(v0, v1);
                *(float2*)&SS[(rl0 + 8) * 68 + cl] = make_float2(v2, v3);
            }
        }
        __syncthreads();

        if (tid < 128) {
            int r = tid;
            float mOld = rowM[r];
            float m = mOld;
            const float4* srow = (const float4*)(SS + r * 68);
#pragma unroll
            for (int jj = 0; jj < 16; jj++) {
                float4 s4 = srow[jj];
                m = fmaxf(m, fmaxf(fmaxf(s4.x, s4.y), fmaxf(s4.z, s4.w)));
            }
            float alpha = __expf(mOld - m);
            float l = 0.f;
#pragma unroll
            for (int jj = 0; jj < 16; jj++) {
                float4 s4 = srow[jj];
                float p0 = __expf(s4.x - m);
                float p1 = __expf(s4.y - m);
                float p2 = __expf(s4.z - m);
                float p3 = __expf(s4.w - m);
                l += (p0 + p1) + (p2 + p3);
                float h0 = ftf32(p0), h1 = ftf32(p1), h2 = ftf32(p2), h3 = ftf32(p3);
                float4 hv = make_float4(h0, h1, h2, h3);
                float4 lv = make_float4(ftf32(p0 - h0), ftf32(p1 - h1),
                                        ftf32(p2 - h2), ftf32(p3 - h3));
                *(float4*)&PH[r * 68 + jj * 4] = hv;
                *(float4*)&PL[r * 68 + jj * 4] = lv;
            }
            rowL[r] = rowL[r] * alpha + l;
            rowM[r] = m;
            rowA[r] = alpha;
        }
        __syncthreads();

#pragma unroll
        for (int mi = 0; mi < 2; mi++) {
            float am0 = rowA[m0 + mi * 16 + gr];
            float am1 = rowA[m0 + mi * 16 + gr + 8];
#pragma unroll
            for (int j = 0; j < 8; j++) {
                o[mi][j][0] *= am0; o[mi][j][1] *= am0;
                o[mi][j][2] *= am1; o[mi][j][3] *= am1;
            }
        }
#pragma unroll
        for (int ks = 0; ks < 8; ks++) {
            uint32_t ap[2][4], alr[2][4];
#pragma unroll
            for (int mi = 0; mi < 2; mi++) {
                int base = (m0 + mi * 16 + gr) * 68 + ks * 8 + tc;
                ap[mi][0]  = __float_as_uint(PH[base]);
                ap[mi][1]  = __float_as_uint(PH[base + 8 * 68]);
                ap[mi][2]  = __float_as_uint(PH[base + 4]);
                ap[mi][3]  = __float_as_uint(PH[base + 8 * 68 + 4]);
                alr[mi][0] = __float_as_uint(PL[base]);
                alr[mi][1] = __float_as_uint(PL[base + 8 * 68]);
                alr[mi][2] = __float_as_uint(PL[base + 4]);
                alr[mi][3] = __float_as_uint(PL[base + 8 * 68 + 4]);
            }
#pragma unroll
            for (int j = 0; j < 8; j++) {
                int base = (nv + j * 8 + gr) * 68 + ks * 8 + tc;
                uint32_t b[2];
                b[0] = __float_as_uint(VT[base]);
                b[1] = __float_as_uint(VT[base + 4]);
#pragma unroll
                for (int mi = 0; mi < 2; mi++) {
                    mma8(o[mi][j], ap[mi], b);
                    mma8(o[mi][j], alr[mi], b);
                }
            }
        }
    }

    // normalize + rna-round + K-PERMUTED store
    const int p0 = (tc < 2) ? 4 * tc     : 4 * tc - 7;
    const int p1 = (tc < 2) ? 4 * tc + 2 : 4 * tc - 5;
#pragma unroll
    for (int mi = 0; mi < 2; mi++) {
        int rl0 = m0 + mi * 16 + gr;
        float inv0 = 1.f / rowL[rl0];
        float inv1 = 1.f / rowL[rl0 + 8];
        int rg0 = qb * 128 + rl0;
#pragma unroll
        for (int j = 0; j < 8; j++) {
            int gbase = h * HD + nv + j * 8;
            float* d0 = out + (size_t)rg0 * DM + gbase;
            float* d1 = out + (size_t)(rg0 + 8) * DM + gbase;
            d0[p0] = ftf32(o[mi][j][0] * inv0);
            d0[p1] = ftf32(o[mi][j][1] * inv0);
            d1[p0] = ftf32(o[mi][j][2] * inv1);
            d1[p1] = ftf32(o[mi][j][3] * inv1);
        }
    }
}

// ===========================================================================
// Host side
// ===========================================================================
extern "C" void kernel_launch(void* const* d_in, const int* in_sizes, int n_in,
                              void* d_out, int out_size)
{
    const float* x     = (const float*)d_in[0];
    const float* w_qkv = (const float*)d_in[2];
    const float* w_out = (const float*)d_in[3];
    float* out = (float*)d_out;

    float *qkv, *attn, *xp, *wqkvp, *woutp;
    cudaGetSymbolAddress((void**)&qkv,   g_qkv);
    cudaGetSymbolAddress((void**)&attn,  g_attn);
    cudaGetSymbolAddress((void**)&xp,    g_xp);
    cudaGetSymbolAddress((void**)&wqkvp, g_wqkvp);
    cudaGetSymbolAddress((void**)&woutp, g_woutp);

    cudaFuncSetAttribute(gemm_mma, cudaFuncAttributeMaxDynamicSharedMemorySize,
                         GEMM_SMEM_BYTES);
    cudaFuncSetAttribute(attn_mma_kernel, cudaFuncAttributeMaxDynamicSharedMemorySize,
                         ATT_SMEM);

    // 0) permute + rna-round GEMM operands
    {
        int n8x = TT * DM / 8;
        perm_round_kernel<<<(n8x + 255) / 256, 256>>>((const float4*)x, (float4*)xp, n8x);
        int n8q = QKV_N * DM / 8;
        perm_round_kernel<<<(n8q + 255) / 256, 256>>>((const float4*)w_qkv, (float4*)wqkvp, n8q);
        int n8o = DM * DM / 8;
        perm_round_kernel<<<(n8o + 255) / 256, 256>>>((const float4*)w_out, (float4*)woutp, n8o);
    }

    // 1) QKV projection + fused RoPE/clamp epilogue
    {
        dim3 grid(QKV_N / 128, TT / 128);
        gemm_mma<<<grid, 256, GEMM_SMEM_BYTES>>>(xp, wqkvp, qkv, QKV_N, DM, 1);
    }

    // 2) Tensor-core flash attention (writes permuted + rounded)
    {
        dim3 grid(TT / 128, NH);
        attn_mma_kernel<<<grid, 256, ATT_SMEM>>>(attn);
    }

    // 3) Output projection
    {
        dim3 grid(DM / 128, TT / 128);
        gemm_mma<<<grid, 256, GEMM_SMEM_BYTES>>>(attn, woutp, out, DM, DM, 0);
    }
}

// round 11
// speedup vs baseline: 1.3992x; 1.0995x over previous
#include <cuda_runtime.h>
#include <cuda_bf16.h>
#include <math.h>
#include <stdint.h>

// Problem constants
#define TT      2048
#define DM      6144
#define NH      48
#define NKV     8
#define HD      128
#define QKV_N   8192
#define KV_OFF  DM
#define V_OFF   (DM + NKV*HD)
#define REP     (NH / NKV)
#define CLAMP_V 8.0f

// Scratch (static device globals)
__device__ float g_qkv[(size_t)TT * QKV_N];
__device__ float g_attn[(size_t)TT * DM];
__device__ float g_xp[(size_t)TT * DM];
__device__ float g_wqkvp[(size_t)QKV_N * DM];
__device__ float g_woutp[(size_t)DM * DM];
__device__ float g_invf[64];

// ===========================================================================
// Helpers
// ===========================================================================
__device__ __forceinline__ uint32_t smem_to_u32(const void* p) {
    uint32_t a;
    asm("{ .reg .u64 t; cvta.to.shared.u64 t, %1; cvt.u32.u64 %0, t; }"
        : "=r"(a) : "l"(p));
    return a;
}
__device__ __forceinline__ void cp16(uint32_t s, const void* g) {
    asm volatile("cp.async.cg.shared.global [%0], [%1], 16;"
                 :: "r"(s), "l"(g) : "memory");
}
__device__ __forceinline__ float ftf32(float x) {
    uint32_t o, i = __float_as_uint(x);
    asm("cvt.rna.tf32.f32 %0, %1;" : "=r"(o) : "r"(i));
    return __uint_as_float(o);
}
__device__ __forceinline__ void mma8(float* d, const uint32_t* a, const uint32_t* b) {
    asm volatile(
        "mma.sync.aligned.m16n8k8.row.col.f32.tf32.tf32.f32 "
        "{%0,%1,%2,%3}, {%4,%5,%6,%7}, {%8,%9}, {%0,%1,%2,%3};"
        : "+f"(d[0]), "+f"(d[1]), "+f"(d[2]), "+f"(d[3])
        : "r"(a[0]), "r"(a[1]), "r"(a[2]), "r"(a[3]), "r"(b[0]), "r"(b[1]));
}
__device__ __forceinline__ void mma16bf(float* d, const uint32_t* a, const uint32_t* b) {
    asm volatile(
        "mma.sync.aligned.m16n8k16.row.col.f32.bf16.bf16.f32 "
        "{%0,%1,%2,%3}, {%4,%5,%6,%7}, {%8,%9}, {%0,%1,%2,%3};"
        : "+f"(d[0]), "+f"(d[1]), "+f"(d[2]), "+f"(d[3])
        : "r"(a[0]), "r"(a[1]), "r"(a[2]), "r"(a[3]), "r"(b[0]), "r"(b[1]));
}
__device__ __forceinline__ uint32_t packsplit(float x, float y, uint32_t& lo) {
    __nv_bfloat16 hx = __float2bfloat16(x);
    __nv_bfloat16 hy = __float2bfloat16(y);
    float rx = x - __bfloat162float(hx);
    float ry = y - __bfloat162float(hy);
    __nv_bfloat16 lx = __float2bfloat16(rx);
    __nv_bfloat16 ly = __float2bfloat16(ry);
    lo = ((uint32_t)__bfloat16_as_ushort(ly) << 16) | __bfloat16_as_ushort(lx);
    return ((uint32_t)__bfloat16_as_ushort(hy) << 16) | __bfloat16_as_ushort(hx);
}
__device__ __forceinline__ float clmp(float v) {
    return fminf(fmaxf(v, -CLAMP_V), CLAMP_V);
}

// ===========================================================================
// inv_freq table (same double-pow formula as before -> bit-identical values)
// ===========================================================================
__global__ void init_invf_kernel()
{
    int i = threadIdx.x;   // 64 threads
    g_invf[i] = (float)pow(500000.0, -(double)i / 64.0);
}

// ===========================================================================
// Permute (within-8 interleave [0,4,1,5,2,6,3,7]) + rna-tf32 round.
// ===========================================================================
__global__ __launch_bounds__(256)
void perm_round_kernel(const float4* __restrict__ src, float4* __restrict__ dst, int n8)
{
    int g = blockIdx.x * blockDim.x + threadIdx.x;
    if (g < n8) {
        float4 i0 = src[2 * g];
        float4 i1 = src[2 * g + 1];
        float4 o0 = make_float4(ftf32(i0.x), ftf32(i1.x), ftf32(i0.y), ftf32(i1.y));
        float4 o1 = make_float4(ftf32(i0.z), ftf32(i1.z), ftf32(i0.w), ftf32(i1.w));
        dst[2 * g]     = o0;
        dst[2 * g + 1] = o1;
    }
}

// ===========================================================================
// tf32 mma.sync GEMM on K-PERMUTED pre-rounded operands.
// CTA tile 128x128, 256 threads (8 warps, warp tile 64x32), 2 CTAs/SM.
// 3-stage cp.async pipeline, ONE __syncthreads per iter. XOR-swizzled SMEM.
// R11: explicit fragment double-buffering (prefetch ks+1 during ks MMAs);
//      RoPE inv_freq from g_invf table (no FP64 in epilogue).
// mode 1: fused RoPE+clamp epilogue.
// ===========================================================================
#define TSZ  (128 * 32)                       // floats per operand per stage (16KB)
#define GEMM_SMEM_BYTES (6 * TSZ * 4)         // 3 stages x 2 operands = 98304

__global__ __launch_bounds__(256, 2)
void gemm_mma(const float* __restrict__ A, const float* __restrict__ B,
              float* __restrict__ C, int N, int K, int mode)
{
    extern __shared__ float sm[];
    const int tid  = threadIdx.x;
    const int wid  = tid >> 5, lane = tid & 31;
    const int wm   = (wid >> 2) * 64;       // 0 / 64
    const int wn   = (wid & 3) * 32;        // 0 / 32 / 64 / 96
    const int gr   = lane >> 2, tc = lane & 3;
    const int bm   = blockIdx.y * 128, bn = blockIdx.x * 128;

    const int ldr = tid >> 3;               // 0..31
    const int ldu = tid & 7;                // float4 unit 0..7

    const uint32_t sbase = smem_to_u32(sm);
    const int NS = K / 32;

    float acc[4][4][4];
#pragma unroll
    for (int i = 0; i < 4; i++)
#pragma unroll
        for (int j = 0; j < 4; j++)
#pragma unroll
            for (int r = 0; r < 4; r++) acc[i][j][r] = 0.f;

    // swizzled float4 unit for the loader (row&3 is constant across v)
    const int lsw = (ldr & 3) << 1;
    const int lu  = (ldu ^ lsw) << 2;       // float offset within row

    auto loadTiles = [&](int k0, int st) {
#pragma unroll
        for (int v = 0; v < 4; v++) {
            int row = ldr + v * 32;
            uint32_t sa = sbase + (uint32_t)(st * TSZ + row * 32 + lu) * 4;
            cp16(sa, A + (size_t)(bm + row) * K + k0 + ldu * 4);
            uint32_t sb = sbase + (uint32_t)(3 * TSZ + st * TSZ + row * 32 + lu) * 4;
            cp16(sb, B + (size_t)(bn + row) * K + k0 + ldu * 4);
        }
        asm volatile("cp.async.commit_group;" ::: "memory");
    };

    loadTiles(0, 0);
    loadTiles(32, 1);

    // Hoisted loop-invariant address components
    const int asw = (gr & 3) << 1;
    const int ain = 2 * (tc & 1);
    int uofs[4];
#pragma unroll
    for (int ks = 0; ks < 4; ks++) {
        int u = 2 * ks + (tc >> 1);
        uofs[ks] = ((u ^ asw) << 2) + ain;
    }
    int arow[4], brow[4];
#pragma unroll
    for (int i = 0; i < 4; i++) arow[i] = (wm + i * 16 + gr) * 32;
#pragma unroll
    for (int j = 0; j < 4; j++) brow[j] = (wn + j * 8 + gr) * 32;

    int st = 0;
    for (int s = 0; s < NS; s++) {
        asm volatile("cp.async.wait_group 1;" ::: "memory");
        __syncthreads();

        int nst = st + 2; if (nst >= 3) nst -= 3;
        if (s + 2 < NS) loadTiles((s + 2) * 32, nst);
        else asm volatile("cp.async.commit_group;" ::: "memory");

        const float* As_ = sm + st * TSZ;
        const float* Bs_ = sm + 3 * TSZ + st * TSZ;

        // fragment double-buffer
        uint32_t afr[2][4][4], bfr[2][4][2];
        auto loadFrags = [&](int ks, uint32_t af[4][4], uint32_t bf[4][2]) {
            const int uof = uofs[ks];
#pragma unroll
            for (int i = 0; i < 4; i++) {
                const float* ap = As_ + arow[i] + uof;
                float2 alo = *(const float2*)(ap);
                float2 ahi = *(const float2*)(ap + 256);
                af[i][0] = __float_as_uint(alo.x);
                af[i][1] = __float_as_uint(ahi.x);
                af[i][2] = __float_as_uint(alo.y);
                af[i][3] = __float_as_uint(ahi.y);
            }
#pragma unroll
            for (int j = 0; j < 4; j++) {
                float2 bv = *(const float2*)(Bs_ + brow[j] + uof);
                bf[j][0] = __float_as_uint(bv.x);
                bf[j][1] = __float_as_uint(bv.y);
            }
        };

        loadFrags(0, afr[0], bfr[0]);
#pragma unroll
        for (int ks = 0; ks < 4; ks++) {
            if (ks < 3) loadFrags(ks + 1, afr[(ks + 1) & 1], bfr[(ks + 1) & 1]);
            uint32_t (*a)[4] = afr[ks & 1];
            uint32_t (*b)[2] = bfr[ks & 1];
#pragma unroll
            for (int i = 0; i < 4; i++)
#pragma unroll
                for (int j = 0; j < 4; j++)
                    mma8(acc[i][j], a[i], b[j]);
        }

        if (++st == 3) st = 0;
    }

    // Epilogue (pairs (c, c+1) per float2 == RoPE pairs when mode==1)
#pragma unroll
    for (int i = 0; i < 4; i++) {
#pragma unroll
        for (int j = 0; j < 4; j++) {
            int r = bm + wm + i * 16 + gr;
            int c = bn + wn + j * 8 + tc * 2;
            float2 v0 = make_float2(acc[i][j][0], acc[i][j][1]);
            float2 v1 = make_float2(acc[i][j][2], acc[i][j][3]);
            if (mode == 1) {
                if (c < V_OFF) {
                    int i64 = (c >> 1) & 63;
                    float inv = g_invf[i64];
                    float s0, c0;
                    sincosf((float)r * inv, &s0, &c0);
                    float a0 = v0.x, b0 = v0.y;
                    v0.x = clmp(a0 * c0 - b0 * s0);
                    v0.y = clmp(a0 * s0 + b0 * c0);
                    float s1, c1;
                    sincosf((float)(r + 8) * inv, &s1, &c1);
                    float a1 = v1.x, b1 = v1.y;
                    v1.x = clmp(a1 * c1 - b1 * s1);
                    v1.y = clmp(a1 * s1 + b1 * c1);
                } else {
                    v0.x = clmp(v0.x); v0.y = clmp(v0.y);
                    v1.x = clmp(v1.x); v1.y = clmp(v1.y);
                }
            }
            *(float2*)&C[(size_t)r * N + c]       = v0;
            *(float2*)&C[(size_t)(r + 8) * N + c] = v1;
        }
    }
}

// ===========================================================================
// Tensor-core flash attention. R11: softmax parallelized across 256 threads
// (2 threads per row, partials combined through smem).
// ===========================================================================
#define A_QH   0
#define A_QL   34816
#define A_KH   69632
#define A_KL   87040
#define A_VT   104448
#define A_VS   139264
#define A_PH   139264
#define A_SS   174080
#define A_PL   174080
#define A_STAT 208896
#define ATT_SMEM 211456

__global__ __launch_bounds__(256, 1)
void attn_mma_kernel(float* __restrict__ out)
{
    extern __shared__ char smem[];
    uint32_t* QHw = (uint32_t*)(smem + A_QH);
    uint32_t* QLw = (uint32_t*)(smem + A_QL);
    uint32_t* KHw = (uint32_t*)(smem + A_KH);
    uint32_t* KLw = (uint32_t*)(smem + A_KL);
    float*    VT  = (float*)(smem + A_VT);
    float*    VS  = (float*)(smem + A_VS);
    float*    PH  = (float*)(smem + A_PH);
    float*    SS  = (float*)(smem + A_SS);
    float*    PL  = SS;
    float* rowM = (float*)(smem + A_STAT);
    float* rowL = rowM + 128;
    float* rowA = rowL + 128;
    float* PPAR = rowA + 128;            // 256 floats

    const int qb   = gridDim.x - 1 - blockIdx.x;
    const int h    = blockIdx.y;
    const int kh   = h / REP;
    const int tid  = threadIdx.x;
    const int wid  = tid >> 5, lane = tid & 31;
    const int gr   = lane >> 2, tc = lane & 3;
    const int m0   = (wid >> 1) * 32;
    const int wn   = (wid & 1) * 32;
    const int nv   = (wid & 1) * 64;
    const float scale = 0.088388347648318447f;

    {
        const float* qg = g_qkv + (size_t)(qb * 128) * QKV_N + h * HD;
#pragma unroll
        for (int i = 0; i < 16; i++) {
            int f = tid + i * 256;
            int r = f >> 5;
            int c = (f & 31) * 4;
            float4 v = *(const float4*)(qg + (size_t)r * QKV_N + c);
            uint32_t l0, l1;
            uint32_t h0 = packsplit(v.x, v.y, l0);
            uint32_t h1 = packsplit(v.z, v.w, l1);
            QHw[r * 68 + c / 2]     = h0;
            QHw[r * 68 + c / 2 + 1] = h1;
            QLw[r * 68 + c / 2]     = l0;
            QLw[r * 68 + c / 2 + 1] = l1;
        }
    }
    if (tid < 128) { rowM[tid] = -1e30f; rowL[tid] = 0.f; }

    float o[2][8][4];
#pragma unroll
    for (int mi = 0; mi < 2; mi++)
#pragma unroll
        for (int j = 0; j < 8; j++)
#pragma unroll
            for (int r = 0; r < 4; r++) o[mi][j][r] = 0.f;

    const int nkt = 2 * qb + 2;
    for (int kt = 0; kt < nkt; kt++) {
        __syncthreads();

        {
            const float* kg = g_qkv + (size_t)(kt * 64) * QKV_N + KV_OFF + kh * HD;
            const float* vg = g_qkv + (size_t)(kt * 64) * QKV_N + V_OFF  + kh * HD;
#pragma unroll
            for (int i = 0; i < 8; i++) {
                int f = tid + i * 256;
                int r = f >> 5;
                int c = (f & 31) * 4;
                float4 kv = *(const float4*)(kg + (size_t)r * QKV_N + c);
                uint32_t l0, l1;
                uint32_t h0 = packsplit(kv.x, kv.y, l0);
                uint32_t h1 = packsplit(kv.z, kv.w, l1);
                KHw[r * 68 + c / 2]     = h0;
                KHw[r * 68 + c / 2 + 1] = h1;
                KLw[r * 68 + c / 2]     = l0;
                KLw[r * 68 + c / 2 + 1] = l1;
                float4 vv = *(const float4*)(vg + (size_t)r * QKV_N + c);
                VS[r * 133 + c + 0] = vv.x;
                VS[r * 133 + c + 1] = vv.y;
                VS[r * 133 + c + 2] = vv.z;
                VS[r * 133 + c + 3] = vv.w;
            }
        }
        __syncthreads();

#pragma unroll
        for (int i = 0; i < 32; i++) {
            int widx = wid + 8 * i;
            int d = widx >> 1;
            int r = (widx & 1) * 32 + lane;
            VT[d * 68 + r] = ftf32(VS[r * 133 + d]);
        }

        float sacc[2][4][4];
#pragma unroll
        for (int mi = 0; mi < 2; mi++)
#pragma unroll
            for (int j = 0; j < 4; j++)
#pragma unroll
                for (int r = 0; r < 4; r++) sacc[mi][j][r] = 0.f;

#pragma unroll
        for (int ks = 0; ks < 8; ks++) {
            uint32_t ah[2][4], al[2][4];
#pragma unroll
            for (int mi = 0; mi < 2; mi++) {
                int base = (m0 + mi * 16 + gr) * 68 + ks * 8 + tc;
                ah[mi][0] = QHw[base];
                ah[mi][1] = QHw[base + 8 * 68];
                ah[mi][2] = QHw[base + 4];
                ah[mi][3] = QHw[base + 8 * 68 + 4];
                al[mi][0] = QLw[base];
                al[mi][1] = QLw[base + 8 * 68];
                al[mi][2] = QLw[base + 4];
                al[mi][3] = QLw[base + 8 * 68 + 4];
            }
            uint32_t bh[4][2], bl[4][2];
#pragma unroll
            for (int j = 0; j < 4; j++) {
                int base = (wn + j * 8 + gr) * 68 + ks * 8 + tc;
                bh[j][0] = KHw[base];
                bh[j][1] = KHw[base + 4];
                bl[j][0] = KLw[base];
                bl[j][1] = KLw[base + 4];
            }
#pragma unroll
            for (int mi = 0; mi < 2; mi++)
#pragma unroll
                for (int j = 0; j < 4; j++) {
                    mma16bf(sacc[mi][j], ah[mi], bh[j]);
                    mma16bf(sacc[mi][j], ah[mi], bl[j]);
                    mma16bf(sacc[mi][j], al[mi], bh[j]);
                }
        }

        const bool dg = (kt >= 2 * qb);
#pragma unroll
        for (int mi = 0; mi < 2; mi++) {
#pragma unroll
            for (int j = 0; j < 4; j++) {
                int rl0 = m0 + mi * 16 + gr;
                int cl  = wn + j * 8 + 2 * tc;
                float v0 = sacc[mi][j][0] * scale;
                float v1 = sacc[mi][j][1] * scale;
                float v2 = sacc[mi][j][2] * scale;
                float v3 = sacc[mi][j][3] * scale;
                if (dg) {
                    int rg0 = qb * 128 + rl0;
                    int cg  = kt * 64 + cl;
                    if (cg     > rg0)     v0 = -1e30f;
                    if (cg + 1 > rg0)     v1 = -1e30f;
                    if (cg     > rg0 + 8) v2 = -1e30f;
                    if (cg + 1 > rg0 + 8) v3 = -1e30f;
                }
                *(float2*)&SS[rl0 * 68 + cl]       = make_float2(v0, v1);
                *(float2*)&SS[(rl0 + 8) * 68 + cl] = make_float2(v2, v3);
            }
        }
        __syncthreads();

        // ---- online softmax, 256 threads: pair (r, r+128) handles row r ----
        {
            const int r  = tid & 127;
            const int hf = tid >> 7;
            const float4* srow = (const float4*)(SS + r * 68) + hf * 8;
            float4 sv[8];
            float pm = -1e30f;
#pragma unroll
            for (int jj = 0; jj < 8; jj++) {
                sv[jj] = srow[jj];
                pm = fmaxf(pm, fmaxf(fmaxf(sv[jj].x, sv[jj].y), fmaxf(sv[jj].z, sv[jj].w)));
            }
            PPAR[tid] = pm;
            __syncthreads();
            float mOld = rowM[r];
            float m = fmaxf(mOld, fmaxf(PPAR[r], PPAR[r + 128]));
            float l = 0.f;
            float* phh = PH + r * 68 + hf * 32;
            float* pll = PL + r * 68 + hf * 32;
#pragma unroll
            for (int jj = 0; jj < 8; jj++) {
                float p0 = __expf(sv[jj].x - m);
                float p1 = __expf(sv[jj].y - m);
                float p2 = __expf(sv[jj].z - m);
                float p3 = __expf(sv[jj].w - m);
                l += (p0 + p1) + (p2 + p3);
                float h0 = ftf32(p0), h1 = ftf32(p1), h2 = ftf32(p2), h3 = ftf32(p3);
                *(float4*)(phh + jj * 4) = make_float4(h0, h1, h2, h3);
                *(float4*)(pll + jj * 4) = make_float4(ftf32(p0 - h0), ftf32(p1 - h1),
                                                       ftf32(p2 - h2), ftf32(p3 - h3));
            }
            PPAR[tid] = l;
            __syncthreads();
            if (tid < 128) {
                float alpha = __expf(mOld - m);
                rowL[r] = rowL[r] * alpha + (PPAR[r] + PPAR[r + 128]);
                rowM[r] = m;
                rowA[r] = alpha;
            }
        }
        __syncthreads();

#pragma unroll
        for (int mi = 0; mi < 2; mi++) {
            float am0 = rowA[m0 + mi * 16 + gr];
            float am1 = rowA[m0 + mi * 16 + gr + 8];
#pragma unroll
            for (int j = 0; j < 8; j++) {
                o[mi][j][0] *= am0; o[mi][j][1] *= am0;
                o[mi][j][2] *= am1; o[mi][j][3] *= am1;
            }
        }
#pragma unroll
        for (int ks = 0; ks < 8; ks++) {
            uint32_t ap[2][4], alr[2][4];
#pragma unroll
            for (int mi = 0; mi < 2; mi++) {
                int base = (m0 + mi * 16 + gr) * 68 + ks * 8 + tc;
                ap[mi][0]  = __float_as_uint(PH[base]);
                ap[mi][1]  = __float_as_uint(PH[base + 8 * 68]);
                ap[mi][2]  = __float_as_uint(PH[base + 4]);
                ap[mi][3]  = __float_as_uint(PH[base + 8 * 68 + 4]);
                alr[mi][0] = __float_as_uint(PL[base]);
                alr[mi][1] = __float_as_uint(PL[base + 8 * 68]);
                alr[mi][2] = __float_as_uint(PL[base + 4]);
                alr[mi][3] = __float_as_uint(PL[base + 8 * 68 + 4]);
            }
#pragma unroll
            for (int j = 0; j < 8; j++) {
                int base = (nv + j * 8 + gr) * 68 + ks * 8 + tc;
                uint32_t b[2];
                b[0] = __float_as_uint(VT[base]);
                b[1] = __float_as_uint(VT[base + 4]);
#pragma unroll
                for (int mi = 0; mi < 2; mi++) {
                    mma8(o[mi][j], ap[mi], b);
                    mma8(o[mi][j], alr[mi], b);
                }
            }
        }
    }

    // normalize + rna-round + K-PERMUTED store
    const int p0 = (tc < 2) ? 4 * tc     : 4 * tc - 7;
    const int p1 = (tc < 2) ? 4 * tc + 2 : 4 * tc - 5;
#pragma unroll
    for (int mi = 0; mi < 2; mi++) {
        int rl0 = m0 + mi * 16 + gr;
        float inv0 = 1.f / rowL[rl0];
        float inv1 = 1.f / rowL[rl0 + 8];
        int rg0 = qb * 128 + rl0;
#pragma unroll
        for (int j = 0; j < 8; j++) {
            int gbase = h * HD + nv + j * 8;
            float* d0 = out + (size_t)rg0 * DM + gbase;
            float* d1 = out + (size_t)(rg0 + 8) * DM + gbase;
            d0[p0] = ftf32(o[mi][j][0] * inv0);
            d0[p1] = ftf32(o[mi][j][1] * inv0);
            d1[p0] = ftf32(o[mi][j][2] * inv1);
            d1[p1] = ftf32(o[mi][j][3] * inv1);
        }
    }
}

// ===========================================================================
// Host side
// ===========================================================================
extern "C" void kernel_launch(void* const* d_in, const int* in_sizes, int n_in,
                              void* d_out, int out_size)
{
    const float* x     = (const float*)d_in[0];
    const float* w_qkv = (const float*)d_in[2];
    const float* w_out = (const float*)d_in[3];
    float* out = (float*)d_out;

    float *qkv, *attn, *xp, *wqkvp, *woutp;
    cudaGetSymbolAddress((void**)&qkv,   g_qkv);
    cudaGetSymbolAddress((void**)&attn,  g_attn);
    cudaGetSymbolAddress((void**)&xp,    g_xp);
    cudaGetSymbolAddress((void**)&wqkvp, g_wqkvp);
    cudaGetSymbolAddress((void**)&woutp, g_woutp);

    cudaFuncSetAttribute(gemm_mma, cudaFuncAttributeMaxDynamicSharedMemorySize,
                         GEMM_SMEM_BYTES);
    cudaFuncSetAttribute(attn_mma_kernel, cudaFuncAttributeMaxDynamicSharedMemorySize,
                         ATT_SMEM);

    // 0) inv_freq table + permute/round GEMM operands
    init_invf_kernel<<<1, 64>>>();
    {
        int n8x = TT * DM / 8;
        perm_round_kernel<<<(n8x + 255) / 256, 256>>>((const float4*)x, (float4*)xp, n8x);
        int n8q = QKV_N * DM / 8;
        perm_round_kernel<<<(n8q + 255) / 256, 256>>>((const float4*)w_qkv, (float4*)wqkvp, n8q);
        int n8o = DM * DM / 8;
        perm_round_kernel<<<(n8o + 255) / 256, 256>>>((const float4*)w_out, (float4*)woutp, n8o);
    }

    // 1) QKV projection + fused RoPE/clamp epilogue
    {
        dim3 grid(QKV_N / 128, TT / 128);
        gemm_mma<<<grid, 256, GEMM_SMEM_BYTES>>>(xp, wqkvp, qkv, QKV_N, DM, 1);
    }

    // 2) Tensor-core flash attention (writes permuted + rounded)
    {
        dim3 grid(TT / 128, NH);
        attn_mma_kernel<<<grid, 256, ATT_SMEM>>>(attn);
    }

    // 3) Output projection
    {
        dim3 grid(DM / 128, TT / 128);
        gemm_mma<<<grid, 256, GEMM_SMEM_BYTES>>>(attn, woutp, out, DM, DM, 0);
    }
}

// round 12
// speedup vs baseline: 1.4197x; 1.0146x over previous
#include <cuda_runtime.h>
#include <cuda_bf16.h>
#include <math.h>
#include <stdint.h>

// Problem constants
#define TT      2048
#define DM      6144
#define NH      48
#define NKV     8
#define HD      128
#define QKV_N   8192
#define KV_OFF  DM
#define V_OFF   (DM + NKV*HD)
#define REP     (NH / NKV)
#define CLAMP_V 8.0f

// Scratch (static device globals)
__device__ float g_qkv[(size_t)TT * QKV_N];
__device__ float g_attn[(size_t)TT * DM];
__device__ float g_xp[(size_t)TT * DM];
__device__ float g_wqkvp[(size_t)QKV_N * DM];
__device__ float g_woutp[(size_t)DM * DM];
__device__ float g_invf[64];

// ===========================================================================
// Helpers
// ===========================================================================
__device__ __forceinline__ uint32_t smem_to_u32(const void* p) {
    uint32_t a;
    asm("{ .reg .u64 t; cvta.to.shared.u64 t, %1; cvt.u32.u64 %0, t; }"
        : "=r"(a) : "l"(p));
    return a;
}
__device__ __forceinline__ void cp16(uint32_t s, const void* g) {
    asm volatile("cp.async.cg.shared.global [%0], [%1], 16;"
                 :: "r"(s), "l"(g) : "memory");
}
__device__ __forceinline__ float ftf32(float x) {
    uint32_t o, i = __float_as_uint(x);
    asm("cvt.rna.tf32.f32 %0, %1;" : "=r"(o) : "r"(i));
    return __uint_as_float(o);
}
__device__ __forceinline__ void mma8(float* d, const uint32_t* a, const uint32_t* b) {
    asm volatile(
        "mma.sync.aligned.m16n8k8.row.col.f32.tf32.tf32.f32 "
        "{%0,%1,%2,%3}, {%4,%5,%6,%7}, {%8,%9}, {%0,%1,%2,%3};"
        : "+f"(d[0]), "+f"(d[1]), "+f"(d[2]), "+f"(d[3])
        : "r"(a[0]), "r"(a[1]), "r"(a[2]), "r"(a[3]), "r"(b[0]), "r"(b[1]));
}
__device__ __forceinline__ void mma16bf(float* d, const uint32_t* a, const uint32_t* b) {
    asm volatile(
        "mma.sync.aligned.m16n8k16.row.col.f32.bf16.bf16.f32 "
        "{%0,%1,%2,%3}, {%4,%5,%6,%7}, {%8,%9}, {%0,%1,%2,%3};"
        : "+f"(d[0]), "+f"(d[1]), "+f"(d[2]), "+f"(d[3])
        : "r"(a[0]), "r"(a[1]), "r"(a[2]), "r"(a[3]), "r"(b[0]), "r"(b[1]));
}
__device__ __forceinline__ uint32_t packsplit(float x, float y, uint32_t& lo) {
    __nv_bfloat16 hx = __float2bfloat16(x);
    __nv_bfloat16 hy = __float2bfloat16(y);
    float rx = x - __bfloat162float(hx);
    float ry = y - __bfloat162float(hy);
    __nv_bfloat16 lx = __float2bfloat16(rx);
    __nv_bfloat16 ly = __float2bfloat16(ry);
    lo = ((uint32_t)__bfloat16_as_ushort(ly) << 16) | __bfloat16_as_ushort(lx);
    return ((uint32_t)__bfloat16_as_ushort(hy) << 16) | __bfloat16_as_ushort(hx);
}
__device__ __forceinline__ float clmp(float v) {
    return fminf(fmaxf(v, -CLAMP_V), CLAMP_V);
}

// ===========================================================================
// inv_freq table
// ===========================================================================
__global__ void init_invf_kernel()
{
    int i = threadIdx.x;
    g_invf[i] = (float)pow(500000.0, -(double)i / 64.0);
}

// ===========================================================================
// Permute (within-8 interleave [0,4,1,5,2,6,3,7]) + rna-tf32 round.
// ===========================================================================
__global__ __launch_bounds__(256)
void perm_round_kernel(const float4* __restrict__ src, float4* __restrict__ dst, int n8)
{
    int g = blockIdx.x * blockDim.x + threadIdx.x;
    if (g < n8) {
        float4 i0 = src[2 * g];
        float4 i1 = src[2 * g + 1];
        float4 o0 = make_float4(ftf32(i0.x), ftf32(i1.x), ftf32(i0.y), ftf32(i1.y));
        float4 o1 = make_float4(ftf32(i0.z), ftf32(i1.z), ftf32(i0.w), ftf32(i1.w));
        dst[2 * g]     = o0;
        dst[2 * g + 1] = o1;
    }
}

// ===========================================================================
// tf32 mma.sync GEMM (unchanged from R11 winner).
// ===========================================================================
#define TSZ  (128 * 32)
#define GEMM_SMEM_BYTES (6 * TSZ * 4)

__global__ __launch_bounds__(256, 2)
void gemm_mma(const float* __restrict__ A, const float* __restrict__ B,
              float* __restrict__ C, int N, int K, int mode)
{
    extern __shared__ float sm[];
    const int tid  = threadIdx.x;
    const int wid  = tid >> 5, lane = tid & 31;
    const int wm   = (wid >> 2) * 64;
    const int wn   = (wid & 3) * 32;
    const int gr   = lane >> 2, tc = lane & 3;
    const int bm   = blockIdx.y * 128, bn = blockIdx.x * 128;

    const int ldr = tid >> 3;
    const int ldu = tid & 7;

    const uint32_t sbase = smem_to_u32(sm);
    const int NS = K / 32;

    float acc[4][4][4];
#pragma unroll
    for (int i = 0; i < 4; i++)
#pragma unroll
        for (int j = 0; j < 4; j++)
#pragma unroll
            for (int r = 0; r < 4; r++) acc[i][j][r] = 0.f;

    const int lsw = (ldr & 3) << 1;
    const int lu  = (ldu ^ lsw) << 2;

    auto loadTiles = [&](int k0, int st) {
#pragma unroll
        for (int v = 0; v < 4; v++) {
            int row = ldr + v * 32;
            uint32_t sa = sbase + (uint32_t)(st * TSZ + row * 32 + lu) * 4;
            cp16(sa, A + (size_t)(bm + row) * K + k0 + ldu * 4);
            uint32_t sb = sbase + (uint32_t)(3 * TSZ + st * TSZ + row * 32 + lu) * 4;
            cp16(sb, B + (size_t)(bn + row) * K + k0 + ldu * 4);
        }
        asm volatile("cp.async.commit_group;" ::: "memory");
    };

    loadTiles(0, 0);
    loadTiles(32, 1);

    const int asw = (gr & 3) << 1;
    const int ain = 2 * (tc & 1);
    int uofs[4];
#pragma unroll
    for (int ks = 0; ks < 4; ks++) {
        int u = 2 * ks + (tc >> 1);
        uofs[ks] = ((u ^ asw) << 2) + ain;
    }
    int arow[4], brow[4];
#pragma unroll
    for (int i = 0; i < 4; i++) arow[i] = (wm + i * 16 + gr) * 32;
#pragma unroll
    for (int j = 0; j < 4; j++) brow[j] = (wn + j * 8 + gr) * 32;

    int st = 0;
    for (int s = 0; s < NS; s++) {
        asm volatile("cp.async.wait_group 1;" ::: "memory");
        __syncthreads();

        int nst = st + 2; if (nst >= 3) nst -= 3;
        if (s + 2 < NS) loadTiles((s + 2) * 32, nst);
        else asm volatile("cp.async.commit_group;" ::: "memory");

        const float* As_ = sm + st * TSZ;
        const float* Bs_ = sm + 3 * TSZ + st * TSZ;

        uint32_t afr[2][4][4], bfr[2][4][2];
        auto loadFrags = [&](int ks, uint32_t af[4][4], uint32_t bf[4][2]) {
            const int uof = uofs[ks];
#pragma unroll
            for (int i = 0; i < 4; i++) {
                const float* ap = As_ + arow[i] + uof;
                float2 alo = *(const float2*)(ap);
                float2 ahi = *(const float2*)(ap + 256);
                af[i][0] = __float_as_uint(alo.x);
                af[i][1] = __float_as_uint(ahi.x);
                af[i][2] = __float_as_uint(alo.y);
                af[i][3] = __float_as_uint(ahi.y);
            }
#pragma unroll
            for (int j = 0; j < 4; j++) {
                float2 bv = *(const float2*)(Bs_ + brow[j] + uof);
                bf[j][0] = __float_as_uint(bv.x);
                bf[j][1] = __float_as_uint(bv.y);
            }
        };

        loadFrags(0, afr[0], bfr[0]);
#pragma unroll
        for (int ks = 0; ks < 4; ks++) {
            if (ks < 3) loadFrags(ks + 1, afr[(ks + 1) & 1], bfr[(ks + 1) & 1]);
            uint32_t (*a)[4] = afr[ks & 1];
            uint32_t (*b)[2] = bfr[ks & 1];
#pragma unroll
            for (int i = 0; i < 4; i++)
#pragma unroll
                for (int j = 0; j < 4; j++)
                    mma8(acc[i][j], a[i], b[j]);
        }

        if (++st == 3) st = 0;
    }

#pragma unroll
    for (int i = 0; i < 4; i++) {
#pragma unroll
        for (int j = 0; j < 4; j++) {
            int r = bm + wm + i * 16 + gr;
            int c = bn + wn + j * 8 + tc * 2;
            float2 v0 = make_float2(acc[i][j][0], acc[i][j][1]);
            float2 v1 = make_float2(acc[i][j][2], acc[i][j][3]);
            if (mode == 1) {
                if (c < V_OFF) {
                    int i64 = (c >> 1) & 63;
                    float inv = g_invf[i64];
                    float s0, c0;
                    sincosf((float)r * inv, &s0, &c0);
                    float a0 = v0.x, b0 = v0.y;
                    v0.x = clmp(a0 * c0 - b0 * s0);
                    v0.y = clmp(a0 * s0 + b0 * c0);
                    float s1, c1;
                    sincosf((float)(r + 8) * inv, &s1, &c1);
                    float a1 = v1.x, b1 = v1.y;
                    v1.x = clmp(a1 * c1 - b1 * s1);
                    v1.y = clmp(a1 * s1 + b1 * c1);
                } else {
                    v0.x = clmp(v0.x); v0.y = clmp(v0.y);
                    v1.x = clmp(v1.x); v1.y = clmp(v1.y);
                }
            }
            *(float2*)&C[(size_t)r * N + c]       = v0;
            *(float2*)&C[(size_t)(r + 8) * N + c] = v1;
        }
    }
}

// ===========================================================================
// Tensor-core flash attention.
// R12: PV via bf16x3 (P and V hi/lo split, 3 cross terms) -- 192 mma16bf
// replaces 256 mma8 per tile; packed bf16x2 P/V^T tiles (pitch 36 words).
// ===========================================================================
#define A_QH   0                      // bf16x2 [128][68w]  34816
#define A_QL   34816
#define A_KH   69632                  // bf16x2 [64][68w]   17408
#define A_KL   87040
#define A_VTH  104448                 // bf16x2 [128][36w]  18432
#define A_VTL  122880
#define A_SS   141312                 // f32 [128][68]      34816
#define A_PHB  176128                 // bf16x2 [128][36w]  18432
#define A_PLB  194560                 // bf16x2 [128][36w]  18432
#define A_VS   176128                 // f32 [64*133] 34048 (aliases PHB/PLB)
#define A_STAT 212992                 // rowM/L/A[128] + PPAR[256] = 2560
#define ATT_SMEM 215552

__global__ __launch_bounds__(256, 1)
void attn_mma_kernel(float* __restrict__ out)
{
    extern __shared__ char smem[];
    uint32_t* QHw = (uint32_t*)(smem + A_QH);
    uint32_t* QLw = (uint32_t*)(smem + A_QL);
    uint32_t* KHw = (uint32_t*)(smem + A_KH);
    uint32_t* KLw = (uint32_t*)(smem + A_KL);
    uint32_t* VTH = (uint32_t*)(smem + A_VTH);
    uint32_t* VTL = (uint32_t*)(smem + A_VTL);
    float*    SS  = (float*)(smem + A_SS);
    uint32_t* PHB = (uint32_t*)(smem + A_PHB);
    uint32_t* PLB = (uint32_t*)(smem + A_PLB);
    float*    VS  = (float*)(smem + A_VS);
    float* rowM = (float*)(smem + A_STAT);
    float* rowL = rowM + 128;
    float* rowA = rowL + 128;
    float* PPAR = rowA + 128;

    const int qb   = gridDim.x - 1 - blockIdx.x;
    const int h    = blockIdx.y;
    const int kh   = h / REP;
    const int tid  = threadIdx.x;
    const int wid  = tid >> 5, lane = tid & 31;
    const int gr   = lane >> 2, tc = lane & 3;
    const int m0   = (wid >> 1) * 32;
    const int wn   = (wid & 1) * 32;
    const int nv   = (wid & 1) * 64;
    const float scale = 0.088388347648318447f;

    {
        const float* qg = g_qkv + (size_t)(qb * 128) * QKV_N + h * HD;
#pragma unroll
        for (int i = 0; i < 16; i++) {
            int f = tid + i * 256;
            int r = f >> 5;
            int c = (f & 31) * 4;
            float4 v = *(const float4*)(qg + (size_t)r * QKV_N + c);
            uint32_t l0, l1;
            uint32_t h0 = packsplit(v.x, v.y, l0);
            uint32_t h1 = packsplit(v.z, v.w, l1);
            QHw[r * 68 + c / 2]     = h0;
            QHw[r * 68 + c / 2 + 1] = h1;
            QLw[r * 68 + c / 2]     = l0;
            QLw[r * 68 + c / 2 + 1] = l1;
        }
    }
    if (tid < 128) { rowM[tid] = -1e30f; rowL[tid] = 0.f; }

    float o[2][8][4];
#pragma unroll
    for (int mi = 0; mi < 2; mi++)
#pragma unroll
        for (int j = 0; j < 8; j++)
#pragma unroll
            for (int r = 0; r < 4; r++) o[mi][j][r] = 0.f;

    const int nkt = 2 * qb + 2;
    for (int kt = 0; kt < nkt; kt++) {
        __syncthreads();   // prev PV done before clobbering K / VS(=PHB/PLB)

        {
            const float* kg = g_qkv + (size_t)(kt * 64) * QKV_N + KV_OFF + kh * HD;
            const float* vg = g_qkv + (size_t)(kt * 64) * QKV_N + V_OFF  + kh * HD;
#pragma unroll
            for (int i = 0; i < 8; i++) {
                int f = tid + i * 256;
                int r = f >> 5;
                int c = (f & 31) * 4;
                float4 kv = *(const float4*)(kg + (size_t)r * QKV_N + c);
                uint32_t l0, l1;
                uint32_t h0 = packsplit(kv.x, kv.y, l0);
                uint32_t h1 = packsplit(kv.z, kv.w, l1);
                KHw[r * 68 + c / 2]     = h0;
                KHw[r * 68 + c / 2 + 1] = h1;
                KLw[r * 68 + c / 2]     = l0;
                KLw[r * 68 + c / 2 + 1] = l1;
                float4 vv = *(const float4*)(vg + (size_t)r * QKV_N + c);
                VS[r * 133 + c + 0] = vv.x;
                VS[r * 133 + c + 1] = vv.y;
                VS[r * 133 + c + 2] = vv.z;
                VS[r * 133 + c + 3] = vv.w;
            }
        }
        __syncthreads();

        // ---- Transpose V + bf16 split: VS[64 kv][133] -> VTH/VTL[128 d][36w] ----
#pragma unroll
        for (int i = 0; i < 16; i++) {
            int idx = tid + i * 256;       // 0..4095
            int d = idx >> 5;              // 0..127
            int w = idx & 31;              // kv pair 0..31
            float v0 = VS[(2 * w) * 133 + d];
            float v1 = VS[(2 * w + 1) * 133 + d];
            uint32_t lo;
            uint32_t hi = packsplit(v0, v1, lo);
            VTH[d * 36 + w] = hi;
            VTL[d * 36 + w] = lo;
        }

        // ---- S = Q K^T (bf16x3) ----
        float sacc[2][4][4];
#pragma unroll
        for (int mi = 0; mi < 2; mi++)
#pragma unroll
            for (int j = 0; j < 4; j++)
#pragma unroll
                for (int r = 0; r < 4; r++) sacc[mi][j][r] = 0.f;

#pragma unroll
        for (int ks = 0; ks < 8; ks++) {
            uint32_t ah[2][4], al[2][4];
#pragma unroll
            for (int mi = 0; mi < 2; mi++) {
                int base = (m0 + mi * 16 + gr) * 68 + ks * 8 + tc;
                ah[mi][0] = QHw[base];
                ah[mi][1] = QHw[base + 8 * 68];
                ah[mi][2] = QHw[base + 4];
                ah[mi][3] = QHw[base + 8 * 68 + 4];
                al[mi][0] = QLw[base];
                al[mi][1] = QLw[base + 8 * 68];
                al[mi][2] = QLw[base + 4];
                al[mi][3] = QLw[base + 8 * 68 + 4];
            }
            uint32_t bh[4][2], bl[4][2];
#pragma unroll
            for (int j = 0; j < 4; j++) {
                int base = (wn + j * 8 + gr) * 68 + ks * 8 + tc;
                bh[j][0] = KHw[base];
                bh[j][1] = KHw[base + 4];
                bl[j][0] = KLw[base];
                bl[j][1] = KLw[base + 4];
            }
#pragma unroll
            for (int mi = 0; mi < 2; mi++)
#pragma unroll
                for (int j = 0; j < 4; j++) {
                    mma16bf(sacc[mi][j], ah[mi], bh[j]);
                    mma16bf(sacc[mi][j], ah[mi], bl[j]);
                    mma16bf(sacc[mi][j], al[mi], bh[j]);
                }
        }

        const bool dg = (kt >= 2 * qb);
#pragma unroll
        for (int mi = 0; mi < 2; mi++) {
#pragma unroll
            for (int j = 0; j < 4; j++) {
                int rl0 = m0 + mi * 16 + gr;
                int cl  = wn + j * 8 + 2 * tc;
                float v0 = sacc[mi][j][0] * scale;
                float v1 = sacc[mi][j][1] * scale;
                float v2 = sacc[mi][j][2] * scale;
                float v3 = sacc[mi][j][3] * scale;
                if (dg) {
                    int rg0 = qb * 128 + rl0;
                    int cg  = kt * 64 + cl;
                    if (cg     > rg0)     v0 = -1e30f;
                    if (cg + 1 > rg0)     v1 = -1e30f;
                    if (cg     > rg0 + 8) v2 = -1e30f;
                    if (cg + 1 > rg0 + 8) v3 = -1e30f;
                }
                *(float2*)&SS[rl0 * 68 + cl]       = make_float2(v0, v1);
                *(float2*)&SS[(rl0 + 8) * 68 + cl] = make_float2(v2, v3);
            }
        }
        __syncthreads();

        // ---- online softmax, 256 threads; write P as packed bf16x2 hi/lo ----
        {
            const int r  = tid & 127;
            const int hf = tid >> 7;
            const float4* srow = (const float4*)(SS + r * 68) + hf * 8;
            float4 sv[8];
            float pm = -1e30f;
#pragma unroll
            for (int jj = 0; jj < 8; jj++) {
                sv[jj] = srow[jj];
                pm = fmaxf(pm, fmaxf(fmaxf(sv[jj].x, sv[jj].y), fmaxf(sv[jj].z, sv[jj].w)));
            }
            PPAR[tid] = pm;
            __syncthreads();
            float mOld = rowM[r];
            float m = fmaxf(mOld, fmaxf(PPAR[r], PPAR[r + 128]));
            float l = 0.f;
            uint32_t* phh = PHB + r * 36 + hf * 16;
            uint32_t* pll = PLB + r * 36 + hf * 16;
#pragma unroll
            for (int jj = 0; jj < 8; jj++) {
                float p0 = __expf(sv[jj].x - m);
                float p1 = __expf(sv[jj].y - m);
                float p2 = __expf(sv[jj].z - m);
                float p3 = __expf(sv[jj].w - m);
                l += (p0 + p1) + (p2 + p3);
                uint32_t lo0, lo1;
                uint32_t h0 = packsplit(p0, p1, lo0);
                uint32_t h1 = packsplit(p2, p3, lo1);
                phh[2 * jj]     = h0;
                phh[2 * jj + 1] = h1;
                pll[2 * jj]     = lo0;
                pll[2 * jj + 1] = lo1;
            }
            PPAR[tid] = l;
            __syncthreads();
            if (tid < 128) {
                float alpha = __expf(mOld - m);
                rowL[r] = rowL[r] * alpha + (PPAR[r] + PPAR[r + 128]);
                rowM[r] = m;
                rowA[r] = alpha;
            }
        }
        __syncthreads();

        // ---- O = alpha*O + P V  (bf16x3) ----
#pragma unroll
        for (int mi = 0; mi < 2; mi++) {
            float am0 = rowA[m0 + mi * 16 + gr];
            float am1 = rowA[m0 + mi * 16 + gr + 8];
#pragma unroll
            for (int j = 0; j < 8; j++) {
                o[mi][j][0] *= am0; o[mi][j][1] *= am0;
                o[mi][j][2] *= am1; o[mi][j][3] *= am1;
            }
        }
#pragma unroll
        for (int ks = 0; ks < 4; ks++) {     // 4 x k16 over 64 kv
            uint32_t aph[2][4], apl[2][4];
#pragma unroll
            for (int mi = 0; mi < 2; mi++) {
                int base = (m0 + mi * 16 + gr) * 36 + ks * 8 + tc;
                aph[mi][0] = PHB[base];
                aph[mi][1] = PHB[base + 8 * 36];
                aph[mi][2] = PHB[base + 4];
                aph[mi][3] = PHB[base + 8 * 36 + 4];
                apl[mi][0] = PLB[base];
                apl[mi][1] = PLB[base + 8 * 36];
                apl[mi][2] = PLB[base + 4];
                apl[mi][3] = PLB[base + 8 * 36 + 4];
            }
#pragma unroll
            for (int j = 0; j < 8; j++) {
                int base = (nv + j * 8 + gr) * 36 + ks * 8 + tc;
                uint32_t bh[2], bl[2];
                bh[0] = VTH[base];
                bh[1] = VTH[base + 4];
                bl[0] = VTL[base];
                bl[1] = VTL[base + 4];
#pragma unroll
                for (int mi = 0; mi < 2; mi++) {
                    mma16bf(o[mi][j], aph[mi], bh);
                    mma16bf(o[mi][j], aph[mi], bl);
                    mma16bf(o[mi][j], apl[mi], bh);
                }
            }
        }
    }

    // normalize + rna-round + K-PERMUTED store
    const int p0 = (tc < 2) ? 4 * tc     : 4 * tc - 7;
    const int p1 = (tc < 2) ? 4 * tc + 2 : 4 * tc - 5;
#pragma unroll
    for (int mi = 0; mi < 2; mi++) {
        int rl0 = m0 + mi * 16 + gr;
        float inv0 = 1.f / rowL[rl0];
        float inv1 = 1.f / rowL[rl0 + 8];
        int rg0 = qb * 128 + rl0;
#pragma unroll
        for (int j = 0; j < 8; j++) {
            int gbase = h * HD + nv + j * 8;
            float* d0 = out + (size_t)rg0 * DM + gbase;
            float* d1 = out + (size_t)(rg0 + 8) * DM + gbase;
            d0[p0] = ftf32(o[mi][j][0] * inv0);
            d0[p1] = ftf32(o[mi][j][1] * inv0);
            d1[p0] = ftf32(o[mi][j][2] * inv1);
            d1[p1] = ftf32(o[mi][j][3] * inv1);
        }
    }
}

// ===========================================================================
// Host side
// ===========================================================================
extern "C" void kernel_launch(void* const* d_in, const int* in_sizes, int n_in,
                              void* d_out, int out_size)
{
    const float* x     = (const float*)d_in[0];
    const float* w_qkv = (const float*)d_in[2];
    const float* w_out = (const float*)d_in[3];
    float* out = (float*)d_out;

    float *qkv, *attn, *xp, *wqkvp, *woutp;
    cudaGetSymbolAddress((void**)&qkv,   g_qkv);
    cudaGetSymbolAddress((void**)&attn,  g_attn);
    cudaGetSymbolAddress((void**)&xp,    g_xp);
    cudaGetSymbolAddress((void**)&wqkvp, g_wqkvp);
    cudaGetSymbolAddress((void**)&woutp, g_woutp);

    cudaFuncSetAttribute(gemm_mma, cudaFuncAttributeMaxDynamicSharedMemorySize,
                         GEMM_SMEM_BYTES);
    cudaFuncSetAttribute(attn_mma_kernel, cudaFuncAttributeMaxDynamicSharedMemorySize,
                         ATT_SMEM);

    // 0) inv_freq table + permute/round GEMM operands
    init_invf_kernel<<<1, 64>>>();
    {
        int n8x = TT * DM / 8;
        perm_round_kernel<<<(n8x + 255) / 256, 256>>>((const float4*)x, (float4*)xp, n8x);
        int n8q = QKV_N * DM / 8;
        perm_round_kernel<<<(n8q + 255) / 256, 256>>>((const float4*)w_qkv, (float4*)wqkvp, n8q);
        int n8o = DM * DM / 8;
        perm_round_kernel<<<(n8o + 255) / 256, 256>>>((const float4*)w_out, (float4*)woutp, n8o);
    }

    // 1) QKV projection + fused RoPE/clamp epilogue
    {
        dim3 grid(QKV_N / 128, TT / 128);
        gemm_mma<<<grid, 256, GEMM_SMEM_BYTES>>>(xp, wqkvp, qkv, QKV_N, DM, 1);
    }

    // 2) Tensor-core flash attention (writes permuted + rounded)
    {
        dim3 grid(TT / 128, NH);
        attn_mma_kernel<<<grid, 256, ATT_SMEM>>>(attn);
    }

    // 3) Output projection
    {
        dim3 grid(DM / 128, TT / 128);
        gemm_mma<<<grid, 256, GEMM_SMEM_BYTES>>>(attn, woutp, out, DM, DM, 0);
    }
}